// round 12
// baseline (speedup 1.0000x reference)
#include <cuda_runtime.h>
#include <cuda_fp16.h>
#include <cstdint>
#include <cstddef>

#define BB   4
#define LL   1024
#define HH   16
#define DD   64
#define EMBN 1024
#define MAXREL 512
#define NREL (2*MAXREL + 1)

#define QB   128
#define SH   72    // half stride, 64-wide buffers (36 words == 4 mod 32)
#define SBW  88    // half stride, band/Q buffer  (44 words == 12 mod 32)
#define SRS  328   // half stride, Srel ring: 256 slots + 63 dup + pad (164 words == 4 mod 32)
#define NEGBIG (-1.25e19f)

// Scratch (allocation-free rule: device globals)
__device__ __half g_qh [BB*LL*HH*DD];
__device__ __half g_kh [BB*LL*HH*DD];
__device__ __half g_vh [BB*LL*HH*DD];
__device__ __half g_ctx[BB*LL*HH*DD];
__device__ __half g_relk_h[NREL*DD];
__device__ __half g_relv_h[NREL*DD];
__device__ __half g_Wfc_h[EMBN*EMBN];
__device__ unsigned long long g_maskb[BB*LL*16];   // 64 k-bits per (row, k-tile)

// ---------------------------------------------------------------------------
#define MMA_F16(d0,d1,d2,d3,a0,a1,a2,a3,b0,b1)                               \
    asm volatile("mma.sync.aligned.m16n8k16.row.col.f32.f16.f16.f32 "        \
                 "{%0,%1,%2,%3}, {%4,%5,%6,%7}, {%8,%9}, {%0,%1,%2,%3};"     \
                 : "+f"(d0), "+f"(d1), "+f"(d2), "+f"(d3)                    \
                 : "r"(a0), "r"(a1), "r"(a2), "r"(a3), "r"(b0), "r"(b1))

#define LDSM_X4(r0,r1,r2,r3,addr)                                            \
    asm volatile("ldmatrix.sync.aligned.m8n8.x4.shared.b16 {%0,%1,%2,%3}, [%4];" \
                 : "=r"(r0), "=r"(r1), "=r"(r2), "=r"(r3) : "r"(addr) : "memory")

#define LDSM_X4_T(r0,r1,r2,r3,addr)                                          \
    asm volatile("ldmatrix.sync.aligned.m8n8.x4.trans.shared.b16 {%0,%1,%2,%3}, [%4];" \
                 : "=r"(r0), "=r"(r1), "=r"(r2), "=r"(r3) : "r"(addr) : "memory")

#define STSM_X4(addr,r0,r1,r2,r3)                                            \
    asm volatile("stmatrix.sync.aligned.m8n8.x4.shared.b16 [%0], {%1,%2,%3,%4};" \
                 :: "r"(addr), "r"(r0), "r"(r1), "r"(r2), "r"(r3) : "memory")

#define CP16(dst,src)                                                        \
    asm volatile("cp.async.cg.shared.global [%0], [%1], 16;" :: "r"(dst), "l"(src))
#define CPCOMMIT()  asm volatile("cp.async.commit_group;")
#define CPWAITALL() asm volatile("cp.async.wait_group 0;" ::: "memory")

__device__ __forceinline__ uint32_t ldh2(const __half* p) { return *(const uint32_t*)p; }
__device__ __forceinline__ uint32_t s2u(const void* p) {
    return (uint32_t)__cvta_generic_to_shared(p);
}
__device__ __forceinline__ int clampdiff(int d) {
    return d < -MAXREL ? -MAXREL : (d > MAXREL ? MAXREL : d);
}
__device__ __forceinline__ uint2 f4_to_h4(float4 v) {
    __half2 h0 = __floats2half2_rn(v.x, v.y);
    __half2 h1 = __floats2half2_rn(v.z, v.w);
    uint2 r; r.x = *(uint32_t*)&h0; r.y = *(uint32_t*)&h1; return r;
}
__device__ __forceinline__ uint32_t h2u(__half2 h) { return *(uint32_t*)&h; }

// ---------------------------------------------------------------------------
// Pre: projections via fp16 mma (y=0..2; Q pre-scaled 0.125) + constants (y=3)
// ---------------------------------------------------------------------------
__global__ __launch_bounds__(256) void pre_kernel(
    const float* __restrict__ query, const float* __restrict__ key_, const float* __restrict__ value,
    const float* __restrict__ Wq, const float* __restrict__ bq,
    const float* __restrict__ Wk, const float* __restrict__ bk,
    const float* __restrict__ Wv, const float* __restrict__ bv,
    const float* __restrict__ relk, const float* __restrict__ relv,
    const float* __restrict__ Wfc,  const int* __restrict__ mask)
{
    const int tid = threadIdx.x;

    if (blockIdx.y == 3) {
        const int stride = 1024 * 256;
        const int base = blockIdx.x * 256 + tid;
        for (int i = base; i < NREL*DD/4; i += stride) {
            float4 a = *(const float4*)(relk + (size_t)i*4);
            float4 b = *(const float4*)(relv + (size_t)i*4);
            *(uint2*)(g_relk_h + (size_t)i*4) = f4_to_h4(a);
            *(uint2*)(g_relv_h + (size_t)i*4) = f4_to_h4(b);
        }
        // tail of rel tables (NREL*DD = 65600 = 16400*4, exact — no tail)
        for (int i = base; i < EMBN*EMBN/4; i += stride) {
            float4 w = *(const float4*)(Wfc + (size_t)i*4);
            *(uint2*)(g_Wfc_h + (size_t)i*4) = f4_to_h4(w);
        }
        for (int i = base; i < BB*LL*16; i += stride) {
            int row = i >> 4, w = i & 15;
            const int* mrow = mask + (size_t)row*LL + w*64;
            unsigned long long bits = 0ull;
            #pragma unroll
            for (int j = 0; j < 16; j++) {
                int4 v = *(const int4*)(mrow + j*4);
                bits |= (unsigned long long)(v.x != 0) << (4*j + 0);
                bits |= (unsigned long long)(v.y != 0) << (4*j + 1);
                bits |= (unsigned long long)(v.z != 0) << (4*j + 2);
                bits |= (unsigned long long)(v.w != 0) << (4*j + 3);
            }
            g_maskb[i] = bits;
        }
        return;
    }

    __shared__ __half Xs[64*SH];
    __shared__ __half Ws[64*SH];
    __shared__ float bs[64];

    const float* X; const float* W; const float* bias; __half* out;
    float oscale = 1.0f;
    if (blockIdx.y == 0)      { X = query; W = Wq; bias = bq; out = g_qh; oscale = 0.125f; }
    else if (blockIdx.y == 1) { X = key_;  W = Wk; bias = bk; out = g_kh; }
    else                      { X = value; W = Wv; bias = bv; out = g_vh; }

    const size_t r0 = (size_t)blockIdx.x * 64;
    const int warp = tid >> 5, lane = tid & 31;
    const int g = lane >> 2, t = lane & 3;
    const int wr = warp >> 2, wc = warp & 3;
    const int l7 = lane & 7, l15 = lane & 15;
    const int lq8 = (lane >> 3) << 3;
    const int lq16 = (lane >> 4) << 3;

    {
        const int rr = tid >> 2, cb = (tid & 3) << 4;
        #pragma unroll
        for (int i = 0; i < 4; i++) {
            float4 v = *(const float4*)(X + (r0 + rr)*64 + cb + i*4);
            *(uint2*)&Xs[rr*SH + cb + i*4] = f4_to_h4(v);
            float4 w = *(const float4*)(W + (size_t)rr*64 + cb + i*4);
            *(uint2*)&Ws[rr*SH + cb + i*4] = f4_to_h4(w);
        }
    }
    if (tid < 64) bs[tid] = bias[tid];
    __syncthreads();

    uint32_t qa[2][4][4];
    #pragma unroll
    for (int mt = 0; mt < 2; mt++)
        #pragma unroll
        for (int ks = 0; ks < 4; ks++) {
            uint32_t ad = s2u(Xs + (wr*32 + mt*16 + l15)*SH + ks*16 + lq16);
            LDSM_X4(qa[mt][ks][0], qa[mt][ks][1], qa[mt][ks][2], qa[mt][ks][3], ad);
        }

    #pragma unroll
    for (int nt = 0; nt < 2; nt++) {
        float c0[4] = {0,0,0,0}, c1[4] = {0,0,0,0};
        #pragma unroll
        for (int ksp = 0; ksp < 2; ksp++) {
            uint32_t b0,b1,b2,b3;
            uint32_t ad = s2u(Ws + (wc*16 + nt*8 + l7)*SH + ksp*32 + lq8);
            LDSM_X4(b0,b1,b2,b3, ad);
            MMA_F16(c0[0],c0[1],c0[2],c0[3], qa[0][2*ksp  ][0],qa[0][2*ksp  ][1],qa[0][2*ksp  ][2],qa[0][2*ksp  ][3], b0,b1);
            MMA_F16(c1[0],c1[1],c1[2],c1[3], qa[1][2*ksp  ][0],qa[1][2*ksp  ][1],qa[1][2*ksp  ][2],qa[1][2*ksp  ][3], b0,b1);
            MMA_F16(c0[0],c0[1],c0[2],c0[3], qa[0][2*ksp+1][0],qa[0][2*ksp+1][1],qa[0][2*ksp+1][2],qa[0][2*ksp+1][3], b2,b3);
            MMA_F16(c1[0],c1[1],c1[2],c1[3], qa[1][2*ksp+1][0],qa[1][2*ksp+1][1],qa[1][2*ksp+1][2],qa[1][2*ksp+1][3], b2,b3);
        }
        const int cb2 = wc*16 + nt*8 + 2*t;
        const float bv0 = bs[cb2], bv1 = bs[cb2 + 1];
        __half2 h00 = __floats2half2_rn((c0[0] + bv0)*oscale, (c0[1] + bv1)*oscale);
        __half2 h01 = __floats2half2_rn((c0[2] + bv0)*oscale, (c0[3] + bv1)*oscale);
        __half2 h10 = __floats2half2_rn((c1[0] + bv0)*oscale, (c1[1] + bv1)*oscale);
        __half2 h11 = __floats2half2_rn((c1[2] + bv0)*oscale, (c1[3] + bv1)*oscale);
        *(uint32_t*)(out + (r0 + wr*32      + g)*64 + cb2) = h2u(h00);
        *(uint32_t*)(out + (r0 + wr*32 +  8 + g)*64 + cb2) = h2u(h01);
        *(uint32_t*)(out + (r0 + wr*32 + 16 + g)*64 + cb2) = h2u(h10);
        *(uint32_t*)(out + (r0 + wr*32 + 24 + g)*64 + cb2) = h2u(h11);
    }
}

// ---------------------------------------------------------------------------
// Attention, flash-v2 with flat mod-256 Srel ring + duplicated tail.
// ---------------------------------------------------------------------------
#define ATT_SMEM_HALFS (128*SRS + 128*SBW + 2*64*SH + 2*64*SH + 2*64*SH + 4*64*SH)
#define ATT_SMEM_BYTES (ATT_SMEM_HALFS*2)

// GEMM over 64-diff relK block -> stmatrix into SrelH at slot base pbS (= diffbase & 255).
// If pbS == 0, also write the duplicate tail at col 256 (slots 0..63 mirrored).
__device__ __forceinline__ void srel_block_gemm(
    const __half* Tk, __half* SrelH, const uint32_t qa[4][4],
    int rw, int pbS, int lane)
{
    const int l7 = lane & 7, l15 = lane & 15;
    const int lq8 = (lane >> 3) << 3;
    const int lq16 = (lane >> 4) << 3;
    #pragma unroll
    for (int npp = 0; npp < 4; npp++) {
        float c0[4] = {0,0,0,0}, c1[4] = {0,0,0,0};
        #pragma unroll
        for (int ksp = 0; ksp < 2; ksp++) {
            uint32_t b0,b1,b2,b3;
            uint32_t ad = s2u(Tk + (npp*16 + l7)*SH + ksp*32 + lq8);
            LDSM_X4(b0,b1,b2,b3, ad);
            MMA_F16(c0[0],c0[1],c0[2],c0[3], qa[2*ksp  ][0],qa[2*ksp  ][1],qa[2*ksp  ][2],qa[2*ksp  ][3], b0,b1);
            MMA_F16(c0[0],c0[1],c0[2],c0[3], qa[2*ksp+1][0],qa[2*ksp+1][1],qa[2*ksp+1][2],qa[2*ksp+1][3], b2,b3);
            uint32_t ad2 = s2u(Tk + (npp*16 + 8 + l7)*SH + ksp*32 + lq8);
            LDSM_X4(b0,b1,b2,b3, ad2);
            MMA_F16(c1[0],c1[1],c1[2],c1[3], qa[2*ksp  ][0],qa[2*ksp  ][1],qa[2*ksp  ][2],qa[2*ksp  ][3], b0,b1);
            MMA_F16(c1[0],c1[1],c1[2],c1[3], qa[2*ksp+1][0],qa[2*ksp+1][1],qa[2*ksp+1][2],qa[2*ksp+1][3], b2,b3);
        }
        __half2 h0 = __floats2half2_rn(c0[0], c0[1]);
        __half2 h1 = __floats2half2_rn(c0[2], c0[3]);
        __half2 h2 = __floats2half2_rn(c1[0], c1[1]);
        __half2 h3 = __floats2half2_rn(c1[2], c1[3]);
        uint32_t sad = s2u(SrelH + (rw + l15)*SRS + pbS + npp*16 + lq16);
        STSM_X4(sad, h2u(h0), h2u(h1), h2u(h2), h2u(h3));
        if (pbS == 0) {
            uint32_t sad2 = s2u(SrelH + (rw + l15)*SRS + 256 + npp*16 + lq16);
            STSM_X4(sad2, h2u(h0), h2u(h1), h2u(h2), h2u(h3));
        }
    }
}

__global__ __launch_bounds__(256, 1) void attn_kernel()
{
    extern __shared__ __half smh[];
    __half* SrelH = smh;                     // 128 x SRS  rel-score ring (256 + 64 dup)
    __half* Bw    = SrelH + 128*SRS;         // 128 x SBW  Q staging, then band (K=80)
    __half* KhB   = Bw    + 128*SBW;         // 2 x 64 x SH  [k][e]
    __half* VhB   = KhB   + 2*64*SH;         // 2 x 64 x SH  [k][d]
    __half* TkB   = VhB   + 2*64*SH;         // 2 x 64 x SH  new relK block [j][e]
    __half* TrvB  = TkB   + 2*64*SH;         // 4 x 64 x SH  relV ring [diff][d]

    const int b  = blockIdx.z;
    const int h  = blockIdx.y;
    const int q0 = blockIdx.x * QB;
    const int tid  = threadIdx.x;
    const int warp = tid >> 5, lane = tid & 31;
    const int g = lane >> 2, t = lane & 3;
    const int l7 = lane & 7, l15 = lane & 15;
    const int lq8  = (lane >> 3) << 3;
    const int lq16 = (lane >> 4) << 3;
    const int tkk = ((lane >> 3) & 1) << 3;
    const int tnn = (lane >> 4) << 3;
    const int rw = warp * 16;

    const int srow = tid >> 3, scol8 = (tid & 7) << 3;
    const int d00 = -q0;

    // ---------------- prologue ----------------
    #pragma unroll
    for (int i = 0; i < 4; i++) {
        int id = tid + i*256;
        int r = id >> 3, c = (id & 7) << 3;
        CP16(s2u(Bw + r*SBW + c),
             g_qh + (((size_t)((b*LL + q0 + r)*HH + h)) << 6) + c);
    }
    #pragma unroll
    for (int half2x = 0; half2x < 2; half2x++) {
        int r = srow + half2x*32;
        CP16(s2u(KhB + r*SH + scol8),
             g_kh + (((size_t)((b*LL + r)*HH + h)) << 6) + scol8);
        CP16(s2u(VhB + r*SH + scol8),
             g_vh + (((size_t)((b*LL + r)*HH + h)) << 6) + scol8);
    }
    #pragma unroll
    for (int half2x = 0; half2x < 2; half2x++) {
        int r = srow + half2x*32;
        int dfA = clampdiff(d00 - 128 + r);
        CP16(s2u(TkB + r*SH + scol8),
             g_relk_h + ((size_t)(dfA + MAXREL) << 6) + scol8);
        int dfB = clampdiff(d00 - 64 + r);
        CP16(s2u(TkB + 64*SH + r*SH + scol8),
             g_relk_h + ((size_t)(dfB + MAXREL) << 6) + scol8);
    }
    #pragma unroll
    for (int bl = 0; bl < 3; bl++) {
        int base = d00 - 128 + bl*64;
        int pb = ((base + 2048) >> 6) & 3;
        #pragma unroll
        for (int half2x = 0; half2x < 2; half2x++) {
            int r = srow + half2x*32;
            int df = clampdiff(base + r);
            CP16(s2u(TrvB + (pb*64 + r)*SH + scol8),
                 g_relv_h + ((size_t)(df + MAXREL) << 6) + scol8);
        }
    }
    CPCOMMIT(); CPWAITALL();
    __syncthreads();

    uint32_t qa[4][4];
    #pragma unroll
    for (int ks = 0; ks < 4; ks++) {
        uint32_t ad = s2u(Bw + (rw + l15)*SBW + ks*16 + lq16);
        LDSM_X4(qa[ks][0], qa[ks][1], qa[ks][2], qa[ks][3], ad);
    }
    __syncthreads();

    {
        const uint4 z = make_uint4(0,0,0,0);
        for (int i = tid; i < 128*SBW/8; i += 256) ((uint4*)Bw)[i] = z;
    }

    // history Srel blocks (slot base = diff base mod 256)
    srel_block_gemm(TkB,         SrelH, qa, rw, (d00 - 128) & 255 & ~63, lane);
    srel_block_gemm(TkB + 64*SH, SrelH, qa, rw, (d00 -  64) & 255 & ~63, lane);
    __syncthreads();

    #pragma unroll
    for (int half2x = 0; half2x < 2; half2x++) {
        int r = srow + half2x*32;
        int df = clampdiff(d00 + r);
        CP16(s2u(TkB + r*SH + scol8),
             g_relk_h + ((size_t)(df + MAXREL) << 6) + scol8);
    }
    CPCOMMIT(); CPWAITALL();
    __syncthreads();

    // ---------------- main loop ----------------
    float oacc[8][4] = {};
    float m0 = -1e30f, m1 = -1e30f, l0 = 0.f, l1 = 0.f;

    for (int kt = 0; kt < 16; kt++) {
        const int k0 = kt * 64;
        const int d0 = k0 - q0;
        const int cs = kt & 1, ns = cs ^ 1;

        unsigned long long bits0 = g_maskb[((size_t)(b*LL + q0 + rw + g    ) << 4) + kt];
        unsigned long long bits1 = g_maskb[((size_t)(b*LL + q0 + rw + g + 8) << 4) + kt];

        if (kt < 15) {
            const int k0n = k0 + 64, dn = d0 + 64;
            const int pbn = ((dn + 2048) >> 6) & 3;
            #pragma unroll
            for (int half2x = 0; half2x < 2; half2x++) {
                int r = srow + half2x*32;
                CP16(s2u(KhB + ns*64*SH + r*SH + scol8),
                     g_kh + (((size_t)((b*LL + k0n + r)*HH + h)) << 6) + scol8);
                CP16(s2u(VhB + ns*64*SH + r*SH + scol8),
                     g_vh + (((size_t)((b*LL + k0n + r)*HH + h)) << 6) + scol8);
                int df = clampdiff(dn + r);
                CP16(s2u(TkB + ns*64*SH + r*SH + scol8),
                     g_relk_h + ((size_t)(df + MAXREL) << 6) + scol8);
                CP16(s2u(TrvB + (pbn*64 + r)*SH + scol8),
                     g_relv_h + ((size_t)(df + MAXREL) << 6) + scol8);
            }
            CPCOMMIT();
        }

        // ---- GEMM1a: QK scores -> registers ----
        float s[8][4] = {};
        #pragma unroll
        for (int np = 0; np < 8; np++) {
            #pragma unroll
            for (int ksp = 0; ksp < 2; ksp++) {
                uint32_t b0,b1,b2,b3;
                uint32_t ad = s2u(KhB + cs*64*SH + (np*8 + l7)*SH + ksp*32 + lq8);
                LDSM_X4(b0,b1,b2,b3, ad);
                MMA_F16(s[np][0],s[np][1],s[np][2],s[np][3],
                        qa[2*ksp  ][0],qa[2*ksp  ][1],qa[2*ksp  ][2],qa[2*ksp  ][3], b0,b1);
                MMA_F16(s[np][0],s[np][1],s[np][2],s[np][3],
                        qa[2*ksp+1][0],qa[2*ksp+1][1],qa[2*ksp+1][2],qa[2*ksp+1][3], b2,b3);
            }
        }
        // ---- GEMM1b: new rel block -> SrelH ring (slot base = d0 mod 256) ----
        srel_block_gemm(TkB + cs*64*SH, SrelH, qa, rw, d0 & 255 & ~63, lane);
        __syncwarp();

        // ---- softmax (warp-local, flat ring addressing) ----
        {
            const __half* rr0 = SrelH + (rw + g    )*SRS + ((d0 - rw - g    ) & 255);
            const __half* rr1 = SrelH + (rw + g + 8)*SRS + ((d0 - rw - g - 8) & 255);
            #pragma unroll
            for (int np = 0; np < 8; np++) {
                #pragma unroll
                for (int i = 0; i < 2; i++) {
                    const int c = np*8 + 2*t + i;
                    float rel0 = __half2float(rr0[c]);
                    float rel1 = __half2float(rr1[c]);
                    float v0 = ((bits0 >> c) & 1ull) ? s[np][i]     : NEGBIG;
                    float v1 = ((bits1 >> c) & 1ull) ? s[np][2 + i] : NEGBIG;
                    s[np][i]     = v0 + rel0;
                    s[np][2 + i] = v1 + rel1;
                }
            }
        }
        float rm0 = -1e30f, rm1 = -1e30f;
        #pragma unroll
        for (int np = 0; np < 8; np++) {
            rm0 = fmaxf(rm0, fmaxf(s[np][0], s[np][1]));
            rm1 = fmaxf(rm1, fmaxf(s[np][2], s[np][3]));
        }
        rm0 = fmaxf(rm0, __shfl_xor_sync(0xffffffffu, rm0, 1));
        rm0 = fmaxf(rm0, __shfl_xor_sync(0xffffffffu, rm0, 2));
        rm1 = fmaxf(rm1, __shfl_xor_sync(0xffffffffu, rm1, 1));
        rm1 = fmaxf(rm1, __shfl_xor_sync(0xffffffffu, rm1, 2));
        float mn0 = fmaxf(m0, rm0), mn1 = fmaxf(m1, rm1);
        float csc0 = __expf(m0 - mn0), csc1 = __expf(m1 - mn1);
        m0 = mn0; m1 = mn1;
        float ls0 = 0.f, ls1 = 0.f;
        #pragma unroll
        for (int np = 0; np < 8; np++) {
            s[np][0] = __expf(s[np][0] - mn0); ls0 += s[np][0];
            s[np][1] = __expf(s[np][1] - mn0); ls0 += s[np][1];
            s[np][2] = __expf(s[np][2] - mn1); ls1 += s[np][2];
            s[np][3] = __expf(s[np][3] - mn1); ls1 += s[np][3];
        }
        ls0 += __shfl_xor_sync(0xffffffffu, ls0, 1);
        ls0 += __shfl_xor_sync(0xffffffffu, ls0, 2);
        ls1 += __shfl_xor_sync(0xffffffffu, ls1, 1);
        ls1 += __shfl_xor_sync(0xffffffffu, ls1, 2);
        l0 = l0*csc0 + ls0;
        l1 = l1*csc1 + ls1;
        #pragma unroll
        for (int np = 0; np < 8; np++) {
            oacc[np][0] *= csc0; oacc[np][1] *= csc0;
            oacc[np][2] *= csc1; oacc[np][3] *= csc1;
        }

        uint32_t pa[4][4];
        #pragma unroll
        for (int ks = 0; ks < 4; ks++) {
            pa[ks][0] = h2u(__floats2half2_rn(s[2*ks  ][0], s[2*ks  ][1]));
            pa[ks][1] = h2u(__floats2half2_rn(s[2*ks  ][2], s[2*ks  ][3]));
            pa[ks][2] = h2u(__floats2half2_rn(s[2*ks+1][0], s[2*ks+1][1]));
            pa[ks][3] = h2u(__floats2half2_rn(s[2*ks+1][2], s[2*ks+1][3]));
        }
        #pragma unroll
        for (int np = 0; np < 8; np++) {
            #pragma unroll
            for (int i = 0; i < 2; i++) {
                const int c = np*8 + 2*t + i;
                Bw[(rw + g    )*SBW + c - g + 15] = __float2half_rn(s[np][i]);
                Bw[(rw + g + 8)*SBW + c - g +  7] = __float2half_rn(s[np][2 + i]);
            }
        }
        __syncwarp();

        // ---- GEMM2a: PV ----
        #pragma unroll
        for (int ks = 0; ks < 4; ks++) {
            #pragma unroll
            for (int ndc = 0; ndc < 4; ndc++) {
                uint32_t b0,b1,b2,b3;
                uint32_t ad = s2u(VhB + cs*64*SH + (ks*16 + tkk + l7)*SH + ndc*16 + tnn);
                LDSM_X4_T(b0,b1,b2,b3, ad);
                MMA_F16(oacc[2*ndc  ][0],oacc[2*ndc  ][1],oacc[2*ndc  ][2],oacc[2*ndc  ][3],
                        pa[ks][0],pa[ks][1],pa[ks][2],pa[ks][3], b0,b1);
                MMA_F16(oacc[2*ndc+1][0],oacc[2*ndc+1][1],oacc[2*ndc+1][2],oacc[2*ndc+1][3],
                        pa[ks][0],pa[ks][1],pa[ks][2],pa[ks][3], b2,b3);
            }
        }
        // ---- GEMM2b: band @ relV ring (K=80) ----
        #pragma unroll
        for (int ks = 0; ks < 5; ks++) {
            uint32_t ua0,ua1,ua2,ua3;
            uint32_t aad = s2u(Bw + (rw + l15)*SBW + ks*16 + lq16);
            LDSM_X4(ua0,ua1,ua2,ua3, aad);
            int dd = d0 - 15 - rw + ks*16 + tkk + l7;
            if (dd > d0 + 63) dd = d0 + 63;
            int dd2 = dd + 2048;
            int prow = ((dd2 >> 6) & 3)*64 + (dd2 & 63);
            const __half* Bb = TrvB + prow*SH + tnn;
            #pragma unroll
            for (int ndc = 0; ndc < 4; ndc++) {
                uint32_t b0,b1,b2,b3;
                LDSM_X4_T(b0,b1,b2,b3, s2u(Bb + ndc*16));
                MMA_F16(oacc[2*ndc  ][0],oacc[2*ndc  ][1],oacc[2*ndc  ][2],oacc[2*ndc  ][3],
                        ua0,ua1,ua2,ua3, b0,b1);
                MMA_F16(oacc[2*ndc+1][0],oacc[2*ndc+1][1],oacc[2*ndc+1][2],oacc[2*ndc+1][3],
                        ua0,ua1,ua2,ua3, b2,b3);
            }
        }

        CPWAITALL();
        __syncthreads();
    }

    // ---- epilogue ----
    {
        const float inv0 = 1.0f / l0;
        const float inv1 = 1.0f / l1;
        const size_t base0 = (((size_t)((b*LL + q0 + rw + g    )*HH + h)) << 6);
        const size_t base1 = (((size_t)((b*LL + q0 + rw + g + 8)*HH + h)) << 6);
        #pragma unroll
        for (int np = 0; np < 8; np++) {
            const int c = np*8 + 2*t;
            __half2 h0 = __floats2half2_rn(oacc[np][0]*inv0, oacc[np][1]*inv0);
            __half2 h1 = __floats2half2_rn(oacc[np][2]*inv1, oacc[np][3]*inv1);
            *(uint32_t*)(g_ctx + base0 + c) = h2u(h0);
            *(uint32_t*)(g_ctx + base1 + c) = h2u(h1);
        }
    }
}

// ---------------------------------------------------------------------------
// Final FC, fp16 mma, 128x128 tiles, 512 threads, 2 CTAs/SM, ldmatrix frags.
// ---------------------------------------------------------------------------
__global__ __launch_bounds__(512, 2) void fc_kernel(
    const float* __restrict__ bfc, float* __restrict__ out)
{
    __shared__ __half Xs[128*SH];
    __shared__ __half Ws[128*SH];

    const int tid  = threadIdx.x;
    const int warp = tid >> 5, lane = tid & 31;
    const int g = lane >> 2, t = lane & 3;
    const int wr = warp >> 2, wc = warp & 3;
    const int l7 = lane & 7, l15 = lane & 15;
    const int lq8 = (lane >> 3) << 3;
    const int lq16 = (lane >> 4) << 3;
    const size_t r0 = (size_t)blockIdx.x * 128;
    const size_t n0 = (size_t)blockIdx.y * 128;

    const int rrA = tid >> 3,         ccA = (tid & 7) << 3;
    const int rrB = (tid + 512) >> 3, ccB = ((tid + 512) & 7) << 3;

    float oacc[2][4][4] = {};
    uint4 pX[2], pW[2];

    *(uint4*)&Xs[rrA*SH + ccA] = *(const uint4*)(g_ctx   + (r0 + rrA)*EMBN + ccA);
    *(uint4*)&Xs[rrB*SH + ccB] = *(const uint4*)(g_ctx   + (r0 + rrB)*EMBN + ccB);
    *(uint4*)&Ws[rrA*SH + ccA] = *(const uint4*)(g_Wfc_h + (n0 + rrA)*EMBN + ccA);
    *(uint4*)&Ws[rrB*SH + ccB] = *(const uint4*)(g_Wfc_h + (n0 + rrB)*EMBN + ccB);

    for (int e = 0; e < 16; e++) {
        __syncthreads();
        if (e < 15) {
            const int e0n = (e + 1) * 64;
            pX[0] = *(const uint4*)(g_ctx   + (r0 + rrA)*EMBN + e0n + ccA);
            pX[1] = *(const uint4*)(g_ctx   + (r0 + rrB)*EMBN + e0n + ccB);
            pW[0] = *(const uint4*)(g_Wfc_h + (n0 + rrA)*EMBN + e0n + ccA);
            pW[1] = *(const uint4*)(g_Wfc_h + (n0 + rrB)*EMBN + e0n + ccB);
        }
        #pragma unroll
        for (int ksp = 0; ksp < 2; ksp++) {
            uint32_t a[2][2][4];
            #pragma unroll
            for (int mi = 0; mi < 2; mi++)
                #pragma unroll
                for (int kk = 0; kk < 2; kk++) {
                    uint32_t ad = s2u(Xs + (wr*32 + mi*16 + l15)*SH + (2*ksp+kk)*16 + lq16);
                    LDSM_X4(a[mi][kk][0], a[mi][kk][1], a[mi][kk][2], a[mi][kk][3], ad);
                }
            #pragma unroll
            for (int nt = 0; nt < 4; nt++) {
                uint32_t b0,b1,b2,b3;
                uint32_t ad = s2u(Ws + (wc*32 + nt*8 + l7)*SH + ksp*32 + lq8);
                LDSM_X4(b0,b1,b2,b3, ad);
                #pragma unroll
                for (int mi = 0; mi < 2; mi++) {
                    MMA_F16(oacc[mi][nt][0], oacc[mi][nt][1], oacc[mi][nt][2], oacc[mi][nt][3],
                            a[mi][0][0], a[mi][0][1], a[mi][0][2], a[mi][0][3], b0, b1);
                    MMA_F16(oacc[mi][nt][0], oacc[mi][nt][1], oacc[mi][nt][2], oacc[mi][nt][3],
                            a[mi][1][0], a[mi][1][1], a[mi][1][2], a[mi][1][3], b2, b3);
                }
            }
        }
        __syncthreads();
        if (e < 15) {
            *(uint4*)&Xs[rrA*SH + ccA] = pX[0];
            *(uint4*)&Xs[rrB*SH + ccB] = pX[1];
            *(uint4*)&Ws[rrA*SH + ccA] = pW[0];
            *(uint4*)&Ws[rrB*SH + ccB] = pW[1];
        }
    }

    #pragma unroll
    for (int mi = 0; mi < 2; mi++) {
        size_t ra = r0 + wr*32 + mi*16 + g;
        #pragma unroll
        for (int nt = 0; nt < 4; nt++) {
            size_t c = n0 + wc*32 + nt*8 + 2*t;
            float bv0 = bfc[c], bv1 = bfc[c+1];
            *(float2*)(out + ra*EMBN + c) =
                make_float2(oacc[mi][nt][0] + bv0, oacc[mi][nt][1] + bv1);
            *(float2*)(out + (ra+8)*EMBN + c) =
                make_float2(oacc[mi][nt][2] + bv0, oacc[mi][nt][3] + bv1);
        }
    }
}

// ---------------------------------------------------------------------------
extern "C" void kernel_launch(void* const* d_in, const int* in_sizes, int n_in,
                              void* d_out, int out_size)
{
    const float* query = (const float*)d_in[0];
    const float* key_  = (const float*)d_in[1];
    const float* value = (const float*)d_in[2];
    const int*   mask  = (const int*)d_in[3];
    const float* Wq = (const float*)d_in[4];
    const float* bq = (const float*)d_in[5];
    const float* Wk = (const float*)d_in[6];
    const float* bk = (const float*)d_in[7];
    const float* Wv = (const float*)d_in[8];
    const float* bv = (const float*)d_in[9];
    const float* Wfc = (const float*)d_in[10];
    const float* bfc = (const float*)d_in[11];
    const float* relk = (const float*)d_in[12];
    const float* relv = (const float*)d_in[13];
    float* out = (float*)d_out;

    cudaFuncSetAttribute(attn_kernel, cudaFuncAttributeMaxDynamicSharedMemorySize, ATT_SMEM_BYTES);

    pre_kernel<<<dim3(1024, 4, 1), 256>>>(query, key_, value, Wq, bq, Wk, bk, Wv, bv,
                                          relk, relv, Wfc, mask);
    attn_kernel<<<dim3(LL/QB, HH, BB), 256, ATT_SMEM_BYTES>>>();
    fc_kernel<<<dim3(32, 8, 1), 512>>>(bfc, out);
}

// round 13
// speedup vs baseline: 1.1409x; 1.1409x over previous
#include <cuda_runtime.h>
#include <cuda_fp16.h>
#include <cstdint>
#include <cstddef>

#define BB   4
#define LL   1024
#define HH   16
#define DD   64
#define EMBN 1024
#define MAXREL 512
#define NREL (2*MAXREL + 1)

#define QB   64
#define SH   72    // half stride (pre/fc smem only)
#define SRS  200   // Srel ring stride: 192 slots + pad (100 words == 4 mod 32)
#define SBW  88    // band/Q buffer stride (44 words == 12 mod 32)
#define NEGBIG (-1.25e19f)

// swizzled stride-64 tile: element (row, col8-group)
#define SWZ(r,c8) (((r) << 6) + ((((c8) ^ ((r) & 7))) << 3))

// Scratch (allocation-free rule: device globals)
__device__ __half g_qh [BB*LL*HH*DD];
__device__ __half g_kh [BB*LL*HH*DD];
__device__ __half g_vh [BB*LL*HH*DD];
__device__ __half g_ctx[BB*LL*HH*DD];
__device__ __half g_relk_h[NREL*DD];
__device__ __half g_relv_h[NREL*DD];
__device__ __half g_Wfc_h[EMBN*EMBN];
__device__ unsigned long long g_maskb[BB*LL*16];   // 64 k-bits per (row, k-tile)

// ---------------------------------------------------------------------------
#define MMA_F16(d0,d1,d2,d3,a0,a1,a2,a3,b0,b1)                               \
    asm volatile("mma.sync.aligned.m16n8k16.row.col.f32.f16.f16.f32 "        \
                 "{%0,%1,%2,%3}, {%4,%5,%6,%7}, {%8,%9}, {%0,%1,%2,%3};"     \
                 : "+f"(d0), "+f"(d1), "+f"(d2), "+f"(d3)                    \
                 : "r"(a0), "r"(a1), "r"(a2), "r"(a3), "r"(b0), "r"(b1))

#define LDSM_X4(r0,r1,r2,r3,addr)                                            \
    asm volatile("ldmatrix.sync.aligned.m8n8.x4.shared.b16 {%0,%1,%2,%3}, [%4];" \
                 : "=r"(r0), "=r"(r1), "=r"(r2), "=r"(r3) : "r"(addr) : "memory")

#define LDSM_X4_T(r0,r1,r2,r3,addr)                                          \
    asm volatile("ldmatrix.sync.aligned.m8n8.x4.trans.shared.b16 {%0,%1,%2,%3}, [%4];" \
                 : "=r"(r0), "=r"(r1), "=r"(r2), "=r"(r3) : "r"(addr) : "memory")

#define STSM_X4(addr,r0,r1,r2,r3)                                            \
    asm volatile("stmatrix.sync.aligned.m8n8.x4.shared.b16 [%0], {%1,%2,%3,%4};" \
                 :: "r"(addr), "r"(r0), "r"(r1), "r"(r2), "r"(r3) : "memory")

#define CP16(dst,src)                                                        \
    asm volatile("cp.async.cg.shared.global [%0], [%1], 16;" :: "r"(dst), "l"(src))
#define CPCOMMIT()  asm volatile("cp.async.commit_group;")
#define CPWAITALL() asm volatile("cp.async.wait_group 0;" ::: "memory")

__device__ __forceinline__ uint32_t ldh2(const __half* p) { return *(const uint32_t*)p; }
__device__ __forceinline__ uint32_t s2u(const void* p) {
    return (uint32_t)__cvta_generic_to_shared(p);
}
__device__ __forceinline__ int clampdiff(int d) {
    return d < -MAXREL ? -MAXREL : (d > MAXREL ? MAXREL : d);
}
__device__ __forceinline__ int m3(int x) { return (x + 48) % 3; }   // x >= -48
__device__ __forceinline__ uint2 f4_to_h4(float4 v) {
    __half2 h0 = __floats2half2_rn(v.x, v.y);
    __half2 h1 = __floats2half2_rn(v.z, v.w);
    uint2 r; r.x = *(uint32_t*)&h0; r.y = *(uint32_t*)&h1; return r;
}
__device__ __forceinline__ uint32_t h2u(__half2 h) { return *(uint32_t*)&h; }

// ---------------------------------------------------------------------------
// Pre: projections via fp16 mma (y=0..2; Q pre-scaled 0.125) + constants (y=3)
// ---------------------------------------------------------------------------
__global__ __launch_bounds__(256) void pre_kernel(
    const float* __restrict__ query, const float* __restrict__ key_, const float* __restrict__ value,
    const float* __restrict__ Wq, const float* __restrict__ bq,
    const float* __restrict__ Wk, const float* __restrict__ bk,
    const float* __restrict__ Wv, const float* __restrict__ bv,
    const float* __restrict__ relk, const float* __restrict__ relv,
    const float* __restrict__ Wfc,  const int* __restrict__ mask)
{
    const int tid = threadIdx.x;

    if (blockIdx.y == 3) {
        const int stride = 1024 * 256;
        const int base = blockIdx.x * 256 + tid;
        for (int i = base; i < NREL*DD/4; i += stride) {
            float4 a = *(const float4*)(relk + (size_t)i*4);
            float4 b = *(const float4*)(relv + (size_t)i*4);
            *(uint2*)(g_relk_h + (size_t)i*4) = f4_to_h4(a);
            *(uint2*)(g_relv_h + (size_t)i*4) = f4_to_h4(b);
        }
        for (int i = base; i < EMBN*EMBN/4; i += stride) {
            float4 w = *(const float4*)(Wfc + (size_t)i*4);
            *(uint2*)(g_Wfc_h + (size_t)i*4) = f4_to_h4(w);
        }
        for (int i = base; i < BB*LL*16; i += stride) {
            int row = i >> 4, w = i & 15;
            const int* mrow = mask + (size_t)row*LL + w*64;
            unsigned long long bits = 0ull;
            #pragma unroll
            for (int j = 0; j < 16; j++) {
                int4 v = *(const int4*)(mrow + j*4);
                bits |= (unsigned long long)(v.x != 0) << (4*j + 0);
                bits |= (unsigned long long)(v.y != 0) << (4*j + 1);
                bits |= (unsigned long long)(v.z != 0) << (4*j + 2);
                bits |= (unsigned long long)(v.w != 0) << (4*j + 3);
            }
            g_maskb[i] = bits;
        }
        return;
    }

    __shared__ __half Xs[64*SH];
    __shared__ __half Ws[64*SH];
    __shared__ float bs[64];

    const float* X; const float* W; const float* bias; __half* out;
    float oscale = 1.0f;
    if (blockIdx.y == 0)      { X = query; W = Wq; bias = bq; out = g_qh; oscale = 0.125f; }
    else if (blockIdx.y == 1) { X = key_;  W = Wk; bias = bk; out = g_kh; }
    else                      { X = value; W = Wv; bias = bv; out = g_vh; }

    const size_t r0 = (size_t)blockIdx.x * 64;
    const int warp = tid >> 5, lane = tid & 31;
    const int g = lane >> 2, t = lane & 3;
    const int wr = warp >> 2, wc = warp & 3;
    const int l7 = lane & 7, l15 = lane & 15;
    const int lq8 = (lane >> 3) << 3;
    const int lq16 = (lane >> 4) << 3;

    {
        const int rr = tid >> 2, cb = (tid & 3) << 4;
        #pragma unroll
        for (int i = 0; i < 4; i++) {
            float4 v = *(const float4*)(X + (r0 + rr)*64 + cb + i*4);
            *(uint2*)&Xs[rr*SH + cb + i*4] = f4_to_h4(v);
            float4 w = *(const float4*)(W + (size_t)rr*64 + cb + i*4);
            *(uint2*)&Ws[rr*SH + cb + i*4] = f4_to_h4(w);
        }
    }
    if (tid < 64) bs[tid] = bias[tid];
    __syncthreads();

    uint32_t qa[2][4][4];
    #pragma unroll
    for (int mt = 0; mt < 2; mt++)
        #pragma unroll
        for (int ks = 0; ks < 4; ks++) {
            uint32_t ad = s2u(Xs + (wr*32 + mt*16 + l15)*SH + ks*16 + lq16);
            LDSM_X4(qa[mt][ks][0], qa[mt][ks][1], qa[mt][ks][2], qa[mt][ks][3], ad);
        }

    #pragma unroll
    for (int nt = 0; nt < 2; nt++) {
        float c0[4] = {0,0,0,0}, c1[4] = {0,0,0,0};
        #pragma unroll
        for (int ksp = 0; ksp < 2; ksp++) {
            uint32_t b0,b1,b2,b3;
            uint32_t ad = s2u(Ws + (wc*16 + nt*8 + l7)*SH + ksp*32 + lq8);
            LDSM_X4(b0,b1,b2,b3, ad);
            MMA_F16(c0[0],c0[1],c0[2],c0[3], qa[0][2*ksp  ][0],qa[0][2*ksp  ][1],qa[0][2*ksp  ][2],qa[0][2*ksp  ][3], b0,b1);
            MMA_F16(c1[0],c1[1],c1[2],c1[3], qa[1][2*ksp  ][0],qa[1][2*ksp  ][1],qa[1][2*ksp  ][2],qa[1][2*ksp  ][3], b0,b1);
            MMA_F16(c0[0],c0[1],c0[2],c0[3], qa[0][2*ksp+1][0],qa[0][2*ksp+1][1],qa[0][2*ksp+1][2],qa[0][2*ksp+1][3], b2,b3);
            MMA_F16(c1[0],c1[1],c1[2],c1[3], qa[1][2*ksp+1][0],qa[1][2*ksp+1][1],qa[1][2*ksp+1][2],qa[1][2*ksp+1][3], b2,b3);
        }
        const int cb2 = wc*16 + nt*8 + 2*t;
        const float bv0 = bs[cb2], bv1 = bs[cb2 + 1];
        __half2 h00 = __floats2half2_rn((c0[0] + bv0)*oscale, (c0[1] + bv1)*oscale);
        __half2 h01 = __floats2half2_rn((c0[2] + bv0)*oscale, (c0[3] + bv1)*oscale);
        __half2 h10 = __floats2half2_rn((c1[0] + bv0)*oscale, (c1[1] + bv1)*oscale);
        __half2 h11 = __floats2half2_rn((c1[2] + bv0)*oscale, (c1[3] + bv1)*oscale);
        *(uint32_t*)(out + (r0 + wr*32      + g)*64 + cb2) = h2u(h00);
        *(uint32_t*)(out + (r0 + wr*32 +  8 + g)*64 + cb2) = h2u(h01);
        *(uint32_t*)(out + (r0 + wr*32 + 16 + g)*64 + cb2) = h2u(h10);
        *(uint32_t*)(out + (r0 + wr*32 + 24 + g)*64 + cb2) = h2u(h11);
    }
}

// ---------------------------------------------------------------------------
// Attention: QB=64, 4 warps, 2 CTAs/SM, swizzled stride-64 tiles, mod-3 rings,
// warp-local no-max softmax, C->A reuse for PV, cp.async double-buffered.
// ---------------------------------------------------------------------------
#define ATT_SMEM_HALFS (64*SRS + 64*SBW + 9*4096)   // 12800 + 5632 + 36864 = 55296
#define ATT_SMEM_BYTES (ATT_SMEM_HALFS*2)           // 110592

// GEMM over one 64-diff relK block (swizzled) -> stmatrix into SrelH at pbS
__device__ __forceinline__ void srel_block_gemm(
    const __half* Tk, __half* SrelH, const uint32_t qa[4][4],
    int rw, int pbS, int lane)
{
    const int l7 = lane & 7, l15 = lane & 15;
    const int lg3 = lane >> 3;            // 0..3 (col8 sub-index)
    const int lq16 = (lane >> 4) << 3;
    #pragma unroll
    for (int npp = 0; npp < 4; npp++) {
        float c0[4] = {0,0,0,0}, c1[4] = {0,0,0,0};
        #pragma unroll
        for (int ksp = 0; ksp < 2; ksp++) {
            uint32_t b0,b1,b2,b3;
            uint32_t ad = s2u(Tk + SWZ(npp*16 + l7, ksp*4 + lg3));
            LDSM_X4(b0,b1,b2,b3, ad);
            MMA_F16(c0[0],c0[1],c0[2],c0[3], qa[2*ksp  ][0],qa[2*ksp  ][1],qa[2*ksp  ][2],qa[2*ksp  ][3], b0,b1);
            MMA_F16(c0[0],c0[1],c0[2],c0[3], qa[2*ksp+1][0],qa[2*ksp+1][1],qa[2*ksp+1][2],qa[2*ksp+1][3], b2,b3);
            uint32_t ad2 = s2u(Tk + SWZ(npp*16 + 8 + l7, ksp*4 + lg3));
            LDSM_X4(b0,b1,b2,b3, ad2);
            MMA_F16(c1[0],c1[1],c1[2],c1[3], qa[2*ksp  ][0],qa[2*ksp  ][1],qa[2*ksp  ][2],qa[2*ksp  ][3], b0,b1);
            MMA_F16(c1[0],c1[1],c1[2],c1[3], qa[2*ksp+1][0],qa[2*ksp+1][1],qa[2*ksp+1][2],qa[2*ksp+1][3], b2,b3);
        }
        __half2 h0 = __floats2half2_rn(c0[0], c0[1]);
        __half2 h1 = __floats2half2_rn(c0[2], c0[3]);
        __half2 h2 = __floats2half2_rn(c1[0], c1[1]);
        __half2 h3 = __floats2half2_rn(c1[2], c1[3]);
        uint32_t sad = s2u(SrelH + (rw + l15)*SRS + pbS + npp*16 + lq16);
        STSM_X4(sad, h2u(h0), h2u(h1), h2u(h2), h2u(h3));
    }
}

__global__ __launch_bounds__(128, 2) void attn_kernel()
{
    extern __shared__ __half smh[];
    __half* SrelH = smh;                     // 64 x SRS   (192-slot mod-3 ring)
    __half* Bw    = SrelH + 64*SRS;          // 64 x SBW   Q staging, then band (K=80)
    __half* KhB   = Bw    + 64*SBW;          // 2 x 64x64  swizzled [k][e]
    __half* VhB   = KhB   + 2*4096;          // 2 x 64x64  swizzled [k][d]
    __half* TkB   = VhB   + 2*4096;          // 2 x 64x64  swizzled relK block [j][e]
    __half* TrvB  = TkB   + 2*4096;          // 3 x 64x64  swizzled relV ring [diff][d]

    const int b  = blockIdx.z;
    const int h  = blockIdx.y;
    const int bx = blockIdx.x;
    const int q0 = bx * QB;
    const int tid  = threadIdx.x;
    const int warp = tid >> 5, lane = tid & 31;
    const int g = lane >> 2, t = lane & 3;
    const int l7 = lane & 7, l15 = lane & 15;
    const int lg3 = lane >> 3;
    const int lq16 = (lane >> 4) << 3;
    const int tkk = ((lane >> 3) & 1) << 3;
    const int tn8 = lane >> 4;               // 0/1 (trans n col8 sub)
    const int rw = warp * 16;
    const int row0 = rw + g, row1 = rw + g + 8;

    const int d00 = -q0;
    const int bb0 = -bx;

    // ---------------- prologue staging ----------------
    #pragma unroll
    for (int i = 0; i < 4; i++) {
        int id = tid + i*128;
        int r = id >> 3, c8 = id & 7, c = c8 << 3;
        // Q -> Bw (unswizzled)
        CP16(s2u(Bw + r*SBW + c),
             g_qh + (((size_t)((b*LL + q0 + r)*HH + h)) << 6) + c);
        // K0, V0
        CP16(s2u(KhB + SWZ(r, c8)),
             g_kh + (((size_t)((b*LL + r)*HH + h)) << 6) + c);
        CP16(s2u(VhB + SWZ(r, c8)),
             g_vh + (((size_t)((b*LL + r)*HH + h)) << 6) + c);
        // TkB[0] = block bb0, TkB[1] = history block bb0-1
        int dfc = clampdiff(d00 + r);
        CP16(s2u(TkB + SWZ(r, c8)),
             g_relk_h + ((size_t)(dfc + MAXREL) << 6) + c);
        int dfh = clampdiff(d00 - 64 + r);
        CP16(s2u(TkB + 4096 + SWZ(r, c8)),
             g_relk_h + ((size_t)(dfh + MAXREL) << 6) + c);
        // TrvB blocks bb0-1, bb0
        CP16(s2u(TrvB + m3(bb0-1)*4096 + SWZ(r, c8)),
             g_relv_h + ((size_t)(dfh + MAXREL) << 6) + c);
        CP16(s2u(TrvB + m3(bb0)*4096 + SWZ(r, c8)),
             g_relv_h + ((size_t)(dfc + MAXREL) << 6) + c);
    }
    CPCOMMIT(); CPWAITALL();
    __syncthreads();

    // Q fragments
    uint32_t qa[4][4];
    #pragma unroll
    for (int ks = 0; ks < 4; ks++) {
        uint32_t ad = s2u(Bw + (rw + l15)*SBW + ks*16 + lq16);
        LDSM_X4(qa[ks][0], qa[ks][1], qa[ks][2], qa[ks][3], ad);
    }
    __syncthreads();   // Bw reusable

    // zero band buffer once
    for (int i = tid; i < 64*SBW/8; i += 128) ((uint4*)Bw)[i] = make_uint4(0,0,0,0);

    // history Srel block (bb0-1)
    srel_block_gemm(TkB + 4096, SrelH, qa, rw, m3(bb0-1)*64, lane);
    __syncthreads();   // TkB[1] free; band zeros visible

    // ---------------- main loop ----------------
    float oacc[8][4] = {};
    float l0 = 0.f, l1 = 0.f;

    for (int kt = 0; kt < 16; kt++) {
        const int k0 = kt * 64;
        const int d0 = k0 - q0;
        const int bb = kt - bx;
        const int cs = kt & 1, ns = cs ^ 1;

        unsigned long long bits0 = g_maskb[((size_t)(b*LL + q0 + row0) << 4) + kt];
        unsigned long long bits1 = g_maskb[((size_t)(b*LL + q0 + row1) << 4) + kt];

        // cp.async staging for tile kt+1
        if (kt < 15) {
            const int k0n = k0 + 64;
            const int trvS = m3(bb + 1)*4096;
            #pragma unroll
            for (int i = 0; i < 4; i++) {
                int id = tid + i*128;
                int r = id >> 3, c8 = id & 7, c = c8 << 3;
                CP16(s2u(KhB + ns*4096 + SWZ(r, c8)),
                     g_kh + (((size_t)((b*LL + k0n + r)*HH + h)) << 6) + c);
                CP16(s2u(VhB + ns*4096 + SWZ(r, c8)),
                     g_vh + (((size_t)((b*LL + k0n + r)*HH + h)) << 6) + c);
                int df = clampdiff(d0 + 64 + r);
                CP16(s2u(TkB + ns*4096 + SWZ(r, c8)),
                     g_relk_h + ((size_t)(df + MAXREL) << 6) + c);
                CP16(s2u(TrvB + trvS + SWZ(r, c8)),
                     g_relv_h + ((size_t)(df + MAXREL) << 6) + c);
            }
            CPCOMMIT();
        }

        // ---- GEMM1a: QK scores -> registers ----
        float s[8][4] = {};
        #pragma unroll
        for (int np = 0; np < 8; np++) {
            #pragma unroll
            for (int ksp = 0; ksp < 2; ksp++) {
                uint32_t b0,b1,b2,b3;
                uint32_t ad = s2u(KhB + cs*4096 + SWZ(np*8 + l7, ksp*4 + lg3));
                LDSM_X4(b0,b1,b2,b3, ad);
                MMA_F16(s[np][0],s[np][1],s[np][2],s[np][3],
                        qa[2*ksp  ][0],qa[2*ksp  ][1],qa[2*ksp  ][2],qa[2*ksp  ][3], b0,b1);
                MMA_F16(s[np][0],s[np][1],s[np][2],s[np][3],
                        qa[2*ksp+1][0],qa[2*ksp+1][1],qa[2*ksp+1][2],qa[2*ksp+1][3], b2,b3);
            }
        }
        // ---- GEMM1b: new rel block -> SrelH ----
        srel_block_gemm(TkB + cs*4096, SrelH, qa, rw, m3(bb)*64, lane);
        __syncwarp();

        // ---- softmax (warp-local, no running max) ----
        {
            const int sLo = m3(bb - 1)*64, sHi = m3(bb)*64;
            const __half* pA0 = SrelH + row0*SRS + sLo + 64 - row0;
            const __half* pB0 = SrelH + row0*SRS + sHi - row0;
            const __half* pA1 = SrelH + row1*SRS + sLo + 64 - row1;
            const __half* pB1 = SrelH + row1*SRS + sHi - row1;
            float ls0 = 0.f, ls1 = 0.f;
            #pragma unroll
            for (int np = 0; np < 8; np++) {
                #pragma unroll
                for (int i = 0; i < 2; i++) {
                    const int c = np*8 + 2*t + i;
                    float rel0 = __half2float((c < row0) ? pA0[c] : pB0[c]);
                    float rel1 = __half2float((c < row1) ? pA1[c] : pB1[c]);
                    float v0 = ((bits0 >> c) & 1ull) ? s[np][i]     : NEGBIG;
                    float v1 = ((bits1 >> c) & 1ull) ? s[np][2 + i] : NEGBIG;
                    float p0 = __expf(v0 + rel0);
                    float p1 = __expf(v1 + rel1);
                    s[np][i] = p0;  s[np][2 + i] = p1;
                    ls0 += p0;      ls1 += p1;
                }
            }
            ls0 += __shfl_xor_sync(0xffffffffu, ls0, 1);
            ls0 += __shfl_xor_sync(0xffffffffu, ls0, 2);
            ls1 += __shfl_xor_sync(0xffffffffu, ls1, 1);
            ls1 += __shfl_xor_sync(0xffffffffu, ls1, 2);
            l0 += ls0;  l1 += ls1;
        }

        // P -> A fragments + band scatter
        uint32_t pa[4][4];
        #pragma unroll
        for (int ks = 0; ks < 4; ks++) {
            pa[ks][0] = h2u(__floats2half2_rn(s[2*ks  ][0], s[2*ks  ][1]));
            pa[ks][1] = h2u(__floats2half2_rn(s[2*ks  ][2], s[2*ks  ][3]));
            pa[ks][2] = h2u(__floats2half2_rn(s[2*ks+1][0], s[2*ks+1][1]));
            pa[ks][3] = h2u(__floats2half2_rn(s[2*ks+1][2], s[2*ks+1][3]));
        }
        #pragma unroll
        for (int np = 0; np < 8; np++) {
            #pragma unroll
            for (int i = 0; i < 2; i++) {
                const int c = np*8 + 2*t + i;
                Bw[row0*SBW + c - g + 15] = __float2half_rn(s[np][i]);
                Bw[row1*SBW + c - g +  7] = __float2half_rn(s[np][2 + i]);
            }
        }
        __syncwarp();

        // ---- GEMM2a: PV (B via ldmatrix.trans on swizzled [k][d]) ----
        #pragma unroll
        for (int ks = 0; ks < 4; ks++) {
            #pragma unroll
            for (int ndc = 0; ndc < 4; ndc++) {
                uint32_t b0,b1,b2,b3;
                uint32_t ad = s2u(VhB + cs*4096 + SWZ(ks*16 + tkk + l7, ndc*2 + tn8));
                LDSM_X4_T(b0,b1,b2,b3, ad);
                MMA_F16(oacc[2*ndc  ][0],oacc[2*ndc  ][1],oacc[2*ndc  ][2],oacc[2*ndc  ][3],
                        pa[ks][0],pa[ks][1],pa[ks][2],pa[ks][3], b0,b1);
                MMA_F16(oacc[2*ndc+1][0],oacc[2*ndc+1][1],oacc[2*ndc+1][2],oacc[2*ndc+1][3],
                        pa[ks][0],pa[ks][1],pa[ks][2],pa[ks][3], b2,b3);
            }
        }
        // ---- GEMM2b: band @ relV ring (K=80) ----
        #pragma unroll
        for (int ks = 0; ks < 5; ks++) {
            uint32_t ua0,ua1,ua2,ua3;
            uint32_t aad = s2u(Bw + (rw + l15)*SBW + ks*16 + lq16);
            LDSM_X4(ua0,ua1,ua2,ua3, aad);
            int dd = d0 - 15 - rw + ks*16 + tkk + l7;
            if (dd > d0 + 63) dd = d0 + 63;       // band col there is always zero
            int bdd = dd >> 6;                     // floor (arithmetic shift)
            int prow = m3(bdd)*64 + (dd & 63);
            #pragma unroll
            for (int ndc = 0; ndc < 4; ndc++) {
                uint32_t b0,b1,b2,b3;
                LDSM_X4_T(b0,b1,b2,b3, s2u(TrvB + SWZ(prow, ndc*2 + tn8)));
                MMA_F16(oacc[2*ndc  ][0],oacc[2*ndc  ][1],oacc[2*ndc  ][2],oacc[2*ndc  ][3],
                        ua0,ua1,ua2,ua3, b0,b1);
                MMA_F16(oacc[2*ndc+1][0],oacc[2*ndc+1][1],oacc[2*ndc+1][2],oacc[2*ndc+1][3],
                        ua0,ua1,ua2,ua3, b2,b3);
            }
        }

        CPWAITALL();
        __syncthreads();
    }

    // ---- epilogue ----
    {
        const float inv0 = 1.0f / l0;
        const float inv1 = 1.0f / l1;
        const size_t base0 = (((size_t)((b*LL + q0 + row0)*HH + h)) << 6);
        const size_t base1 = (((size_t)((b*LL + q0 + row1)*HH + h)) << 6);
        #pragma unroll
        for (int np = 0; np < 8; np++) {
            const int c = np*8 + 2*t;
            __half2 h0 = __floats2half2_rn(oacc[np][0]*inv0, oacc[np][1]*inv0);
            __half2 h1 = __floats2half2_rn(oacc[np][2]*inv1, oacc[np][3]*inv1);
            *(uint32_t*)(g_ctx + base0 + c) = h2u(h0);
            *(uint32_t*)(g_ctx + base1 + c) = h2u(h1);
        }
    }
}

// ---------------------------------------------------------------------------
// Final FC, fp16 mma, 128x128 tiles, 512 threads, 2 CTAs/SM, ldmatrix frags.
// ---------------------------------------------------------------------------
__global__ __launch_bounds__(512, 2) void fc_kernel(
    const float* __restrict__ bfc, float* __restrict__ out)
{
    __shared__ __half Xs[128*SH];
    __shared__ __half Ws[128*SH];

    const int tid  = threadIdx.x;
    const int warp = tid >> 5, lane = tid & 31;
    const int g = lane >> 2, t = lane & 3;
    const int wr = warp >> 2, wc = warp & 3;
    const int l7 = lane & 7, l15 = lane & 15;
    const int lq8 = (lane >> 3) << 3;
    const int lq16 = (lane >> 4) << 3;
    const size_t r0 = (size_t)blockIdx.x * 128;
    const size_t n0 = (size_t)blockIdx.y * 128;

    const int rrA = tid >> 3,         ccA = (tid & 7) << 3;
    const int rrB = (tid + 512) >> 3, ccB = ((tid + 512) & 7) << 3;

    float oacc[2][4][4] = {};
    uint4 pX[2], pW[2];

    *(uint4*)&Xs[rrA*SH + ccA] = *(const uint4*)(g_ctx   + (r0 + rrA)*EMBN + ccA);
    *(uint4*)&Xs[rrB*SH + ccB] = *(const uint4*)(g_ctx   + (r0 + rrB)*EMBN + ccB);
    *(uint4*)&Ws[rrA*SH + ccA] = *(const uint4*)(g_Wfc_h + (n0 + rrA)*EMBN + ccA);
    *(uint4*)&Ws[rrB*SH + ccB] = *(const uint4*)(g_Wfc_h + (n0 + rrB)*EMBN + ccB);

    for (int e = 0; e < 16; e++) {
        __syncthreads();
        if (e < 15) {
            const int e0n = (e + 1) * 64;
            pX[0] = *(const uint4*)(g_ctx   + (r0 + rrA)*EMBN + e0n + ccA);
            pX[1] = *(const uint4*)(g_ctx   + (r0 + rrB)*EMBN + e0n + ccB);
            pW[0] = *(const uint4*)(g_Wfc_h + (n0 + rrA)*EMBN + e0n + ccA);
            pW[1] = *(const uint4*)(g_Wfc_h + (n0 + rrB)*EMBN + e0n + ccB);
        }
        #pragma unroll
        for (int ksp = 0; ksp < 2; ksp++) {
            uint32_t a[2][2][4];
            #pragma unroll
            for (int mi = 0; mi < 2; mi++)
                #pragma unroll
                for (int kk = 0; kk < 2; kk++) {
                    uint32_t ad = s2u(Xs + (wr*32 + mi*16 + l15)*SH + (2*ksp+kk)*16 + lq16);
                    LDSM_X4(a[mi][kk][0], a[mi][kk][1], a[mi][kk][2], a[mi][kk][3], ad);
                }
            #pragma unroll
            for (int nt = 0; nt < 4; nt++) {
                uint32_t b0,b1,b2,b3;
                uint32_t ad = s2u(Ws + (wc*32 + nt*8 + l7)*SH + ksp*32 + lq8);
                LDSM_X4(b0,b1,b2,b3, ad);
                #pragma unroll
                for (int mi = 0; mi < 2; mi++) {
                    MMA_F16(oacc[mi][nt][0], oacc[mi][nt][1], oacc[mi][nt][2], oacc[mi][nt][3],
                            a[mi][0][0], a[mi][0][1], a[mi][0][2], a[mi][0][3], b0, b1);
                    MMA_F16(oacc[mi][nt][0], oacc[mi][nt][1], oacc[mi][nt][2], oacc[mi][nt][3],
                            a[mi][1][0], a[mi][1][1], a[mi][1][2], a[mi][1][3], b2, b3);
                }
            }
        }
        __syncthreads();
        if (e < 15) {
            *(uint4*)&Xs[rrA*SH + ccA] = pX[0];
            *(uint4*)&Xs[rrB*SH + ccB] = pX[1];
            *(uint4*)&Ws[rrA*SH + ccA] = pW[0];
            *(uint4*)&Ws[rrB*SH + ccB] = pW[1];
        }
    }

    #pragma unroll
    for (int mi = 0; mi < 2; mi++) {
        size_t ra = r0 + wr*32 + mi*16 + g;
        #pragma unroll
        for (int nt = 0; nt < 4; nt++) {
            size_t c = n0 + wc*32 + nt*8 + 2*t;
            float bv0 = bfc[c], bv1 = bfc[c+1];
            *(float2*)(out + ra*EMBN + c) =
                make_float2(oacc[mi][nt][0] + bv0, oacc[mi][nt][1] + bv1);
            *(float2*)(out + (ra+8)*EMBN + c) =
                make_float2(oacc[mi][nt][2] + bv0, oacc[mi][nt][3] + bv1);
        }
    }
}

// ---------------------------------------------------------------------------
extern "C" void kernel_launch(void* const* d_in, const int* in_sizes, int n_in,
                              void* d_out, int out_size)
{
    const float* query = (const float*)d_in[0];
    const float* key_  = (const float*)d_in[1];
    const float* value = (const float*)d_in[2];
    const int*   mask  = (const int*)d_in[3];
    const float* Wq = (const float*)d_in[4];
    const float* bq = (const float*)d_in[5];
    const float* Wk = (const float*)d_in[6];
    const float* bk = (const float*)d_in[7];
    const float* Wv = (const float*)d_in[8];
    const float* bv = (const float*)d_in[9];
    const float* Wfc = (const float*)d_in[10];
    const float* bfc = (const float*)d_in[11];
    const float* relk = (const float*)d_in[12];
    const float* relv = (const float*)d_in[13];
    float* out = (float*)d_out;

    cudaFuncSetAttribute(attn_kernel, cudaFuncAttributeMaxDynamicSharedMemorySize, ATT_SMEM_BYTES);

    pre_kernel<<<dim3(1024, 4, 1), 256>>>(query, key_, value, Wq, bq, Wk, bk, Wv, bv,
                                          relk, relv, Wfc, mask);
    attn_kernel<<<dim3(LL/QB, HH, BB), 128, ATT_SMEM_BYTES>>>();
    fc_kernel<<<dim3(32, 8, 1), 512>>>(bfc, out);
}

// round 14
// speedup vs baseline: 1.1768x; 1.0314x over previous
#include <cuda_runtime.h>
#include <cuda_fp16.h>
#include <cstdint>
#include <cstddef>

#define BB   4
#define LL   1024
#define HH   16
#define DD   64
#define EMBN 1024
#define MAXREL 512
#define NREL (2*MAXREL + 1)

#define QB   64
#define SH   72    // half stride (pre smem)
#define SRS  200   // Srel ring stride: 192 slots + pad (100 words == 4 mod 32)
#define SBW  88    // band/Q buffer stride (44 words == 12 mod 32)
#define NEGBIG (-1.25e19f)

// swizzled stride-64 tile: element (row, col8-group)
#define SWZ(r,c8) (((r) << 6) + ((((c8) ^ ((r) & 7))) << 3))

// Scratch (allocation-free rule: device globals)
__device__ __half g_qh [BB*LL*HH*DD];
__device__ __half g_kh [BB*LL*HH*DD];
__device__ __half g_vh [BB*LL*HH*DD];
__device__ __half g_ctx[BB*LL*HH*DD];
__device__ __half g_relk_h[NREL*DD];
__device__ __half g_relv_h[NREL*DD];
__device__ __half g_Wfc_h[EMBN*EMBN];
__device__ unsigned long long g_maskb[BB*LL*16];   // 64 k-bits per (row, k-tile)

// ---------------------------------------------------------------------------
#define MMA_F16(d0,d1,d2,d3,a0,a1,a2,a3,b0,b1)                               \
    asm volatile("mma.sync.aligned.m16n8k16.row.col.f32.f16.f16.f32 "        \
                 "{%0,%1,%2,%3}, {%4,%5,%6,%7}, {%8,%9}, {%0,%1,%2,%3};"     \
                 : "+f"(d0), "+f"(d1), "+f"(d2), "+f"(d3)                    \
                 : "r"(a0), "r"(a1), "r"(a2), "r"(a3), "r"(b0), "r"(b1))

#define LDSM_X4(r0,r1,r2,r3,addr)                                            \
    asm volatile("ldmatrix.sync.aligned.m8n8.x4.shared.b16 {%0,%1,%2,%3}, [%4];" \
                 : "=r"(r0), "=r"(r1), "=r"(r2), "=r"(r3) : "r"(addr) : "memory")

#define LDSM_X4_T(r0,r1,r2,r3,addr)                                          \
    asm volatile("ldmatrix.sync.aligned.m8n8.x4.trans.shared.b16 {%0,%1,%2,%3}, [%4];" \
                 : "=r"(r0), "=r"(r1), "=r"(r2), "=r"(r3) : "r"(addr) : "memory")

#define STSM_X4(addr,r0,r1,r2,r3)                                            \
    asm volatile("stmatrix.sync.aligned.m8n8.x4.shared.b16 [%0], {%1,%2,%3,%4};" \
                 :: "r"(addr), "r"(r0), "r"(r1), "r"(r2), "r"(r3) : "memory")

#define CP16(dst,src)                                                        \
    asm volatile("cp.async.cg.shared.global [%0], [%1], 16;" :: "r"(dst), "l"(src))
#define CPCOMMIT()  asm volatile("cp.async.commit_group;")
#define CPWAITALL() asm volatile("cp.async.wait_group 0;" ::: "memory")
#define CPWAIT1()   asm volatile("cp.async.wait_group 1;" ::: "memory")

__device__ __forceinline__ uint32_t ldh2(const __half* p) { return *(const uint32_t*)p; }
__device__ __forceinline__ uint32_t s2u(const void* p) {
    return (uint32_t)__cvta_generic_to_shared(p);
}
__device__ __forceinline__ int clampdiff(int d) {
    return d < -MAXREL ? -MAXREL : (d > MAXREL ? MAXREL : d);
}
__device__ __forceinline__ int m3(int x) { return (x + 48) % 3; }   // x >= -48
__device__ __forceinline__ uint2 f4_to_h4(float4 v) {
    __half2 h0 = __floats2half2_rn(v.x, v.y);
    __half2 h1 = __floats2half2_rn(v.z, v.w);
    uint2 r; r.x = *(uint32_t*)&h0; r.y = *(uint32_t*)&h1; return r;
}
__device__ __forceinline__ uint32_t h2u(__half2 h) { return *(uint32_t*)&h; }

// ---------------------------------------------------------------------------
// Pre: y=0 -> ALL THREE projections per 64-row block (high-MLP staging);
//      y=1 -> fp16 constant conversion + mask bit-pack.
// ---------------------------------------------------------------------------
#define PRE_SMEM_BYTES (3*64*SH*2*2 + 192*4)

__global__ __launch_bounds__(256) void pre_kernel(
    const float* __restrict__ query, const float* __restrict__ key_, const float* __restrict__ value,
    const float* __restrict__ Wq, const float* __restrict__ bq,
    const float* __restrict__ Wk, const float* __restrict__ bk,
    const float* __restrict__ Wv, const float* __restrict__ bv,
    const float* __restrict__ relk, const float* __restrict__ relv,
    const float* __restrict__ Wfc,  const int* __restrict__ mask)
{
    const int tid = threadIdx.x;

    if (blockIdx.y == 1) {
        const int stride = 1024 * 256;
        const int base = blockIdx.x * 256 + tid;
        for (int i = base; i < NREL*DD/4; i += stride) {
            float4 a = *(const float4*)(relk + (size_t)i*4);
            float4 b = *(const float4*)(relv + (size_t)i*4);
            *(uint2*)(g_relk_h + (size_t)i*4) = f4_to_h4(a);
            *(uint2*)(g_relv_h + (size_t)i*4) = f4_to_h4(b);
        }
        for (int i = base; i < EMBN*EMBN/4; i += stride) {
            float4 w = *(const float4*)(Wfc + (size_t)i*4);
            *(uint2*)(g_Wfc_h + (size_t)i*4) = f4_to_h4(w);
        }
        for (int i = base; i < BB*LL*16; i += stride) {
            int row = i >> 4, w = i & 15;
            const int* mrow = mask + (size_t)row*LL + w*64;
            unsigned long long bits = 0ull;
            #pragma unroll
            for (int j = 0; j < 16; j++) {
                int4 v = *(const int4*)(mrow + j*4);
                bits |= (unsigned long long)(v.x != 0) << (4*j + 0);
                bits |= (unsigned long long)(v.y != 0) << (4*j + 1);
                bits |= (unsigned long long)(v.z != 0) << (4*j + 2);
                bits |= (unsigned long long)(v.w != 0) << (4*j + 3);
            }
            g_maskb[i] = bits;
        }
        return;
    }

    extern __shared__ __half presm[];
    __half* Xs = presm;                 // 3 x 64 x SH
    __half* Ws = Xs + 3*64*SH;          // 3 x 64 x SH
    float*  bs = (float*)(Ws + 3*64*SH); // 3 x 64

    const float* Xa[3] = {query, key_, value};
    const float* Wa[3] = {Wq, Wk, Wv};
    __half* oa[3] = {g_qh, g_kh, g_vh};

    const size_t r0 = (size_t)blockIdx.x * 64;
    const int warp = tid >> 5, lane = tid & 31;
    const int g = lane >> 2, t = lane & 3;
    const int wr = warp >> 2, wc = warp & 3;
    const int l7 = lane & 7, l15 = lane & 15;
    const int lq8 = (lane >> 3) << 3;
    const int lq16 = (lane >> 4) << 3;

    // stage all 3 X tiles + all 3 W tiles (24 float4 LDGs in flight per thread)
    {
        const int rr = tid >> 2, cb = (tid & 3) << 4;
        #pragma unroll
        for (int arr = 0; arr < 3; arr++) {
            #pragma unroll
            for (int i = 0; i < 4; i++) {
                float4 v = *(const float4*)(Xa[arr] + (r0 + rr)*64 + cb + i*4);
                *(uint2*)&Xs[arr*64*SH + rr*SH + cb + i*4] = f4_to_h4(v);
                float4 w = *(const float4*)(Wa[arr] + (size_t)rr*64 + cb + i*4);
                *(uint2*)&Ws[arr*64*SH + rr*SH + cb + i*4] = f4_to_h4(w);
            }
        }
    }
    if (tid < 64) {
        bs[tid]       = bq[tid];
        bs[64 + tid]  = bk[tid];
        bs[128 + tid] = bv[tid];
    }
    __syncthreads();

    for (int arr = 0; arr < 3; arr++) {
        const __half* Xb = Xs + arr*64*SH;
        const __half* Wb = Ws + arr*64*SH;
        const float*  bb = bs + arr*64;
        __half* out = oa[arr];
        const float oscale = (arr == 0) ? 0.125f : 1.0f;

        uint32_t qa[2][4][4];
        #pragma unroll
        for (int mt = 0; mt < 2; mt++)
            #pragma unroll
            for (int ks = 0; ks < 4; ks++) {
                uint32_t ad = s2u(Xb + (wr*32 + mt*16 + l15)*SH + ks*16 + lq16);
                LDSM_X4(qa[mt][ks][0], qa[mt][ks][1], qa[mt][ks][2], qa[mt][ks][3], ad);
            }

        #pragma unroll
        for (int nt = 0; nt < 2; nt++) {
            float c0[4] = {0,0,0,0}, c1[4] = {0,0,0,0};
            #pragma unroll
            for (int ksp = 0; ksp < 2; ksp++) {
                uint32_t b0,b1,b2,b3;
                uint32_t ad = s2u(Wb + (wc*16 + nt*8 + l7)*SH + ksp*32 + lq8);
                LDSM_X4(b0,b1,b2,b3, ad);
                MMA_F16(c0[0],c0[1],c0[2],c0[3], qa[0][2*ksp  ][0],qa[0][2*ksp  ][1],qa[0][2*ksp  ][2],qa[0][2*ksp  ][3], b0,b1);
                MMA_F16(c1[0],c1[1],c1[2],c1[3], qa[1][2*ksp  ][0],qa[1][2*ksp  ][1],qa[1][2*ksp  ][2],qa[1][2*ksp  ][3], b0,b1);
                MMA_F16(c0[0],c0[1],c0[2],c0[3], qa[0][2*ksp+1][0],qa[0][2*ksp+1][1],qa[0][2*ksp+1][2],qa[0][2*ksp+1][3], b2,b3);
                MMA_F16(c1[0],c1[1],c1[2],c1[3], qa[1][2*ksp+1][0],qa[1][2*ksp+1][1],qa[1][2*ksp+1][2],qa[1][2*ksp+1][3], b2,b3);
            }
            const int cb2 = wc*16 + nt*8 + 2*t;
            const float bv0 = bb[cb2], bv1 = bb[cb2 + 1];
            __half2 h00 = __floats2half2_rn((c0[0] + bv0)*oscale, (c0[1] + bv1)*oscale);
            __half2 h01 = __floats2half2_rn((c0[2] + bv0)*oscale, (c0[3] + bv1)*oscale);
            __half2 h10 = __floats2half2_rn((c1[0] + bv0)*oscale, (c1[1] + bv1)*oscale);
            __half2 h11 = __floats2half2_rn((c1[2] + bv0)*oscale, (c1[3] + bv1)*oscale);
            *(uint32_t*)(out + (r0 + wr*32      + g)*64 + cb2) = h2u(h00);
            *(uint32_t*)(out + (r0 + wr*32 +  8 + g)*64 + cb2) = h2u(h01);
            *(uint32_t*)(out + (r0 + wr*32 + 16 + g)*64 + cb2) = h2u(h10);
            *(uint32_t*)(out + (r0 + wr*32 + 24 + g)*64 + cb2) = h2u(h11);
        }
    }
}

// ---------------------------------------------------------------------------
// Attention (unchanged from round 13): QB=64, 4 warps, 2 CTAs/SM.
// ---------------------------------------------------------------------------
#define ATT_SMEM_HALFS (64*SRS + 64*SBW + 9*4096)
#define ATT_SMEM_BYTES (ATT_SMEM_HALFS*2)

__device__ __forceinline__ void srel_block_gemm(
    const __half* Tk, __half* SrelH, const uint32_t qa[4][4],
    int rw, int pbS, int lane)
{
    const int l7 = lane & 7, l15 = lane & 15;
    const int lg3 = lane >> 3;
    const int lq16 = (lane >> 4) << 3;
    #pragma unroll
    for (int npp = 0; npp < 4; npp++) {
        float c0[4] = {0,0,0,0}, c1[4] = {0,0,0,0};
        #pragma unroll
        for (int ksp = 0; ksp < 2; ksp++) {
            uint32_t b0,b1,b2,b3;
            uint32_t ad = s2u(Tk + SWZ(npp*16 + l7, ksp*4 + lg3));
            LDSM_X4(b0,b1,b2,b3, ad);
            MMA_F16(c0[0],c0[1],c0[2],c0[3], qa[2*ksp  ][0],qa[2*ksp  ][1],qa[2*ksp  ][2],qa[2*ksp  ][3], b0,b1);
            MMA_F16(c0[0],c0[1],c0[2],c0[3], qa[2*ksp+1][0],qa[2*ksp+1][1],qa[2*ksp+1][2],qa[2*ksp+1][3], b2,b3);
            uint32_t ad2 = s2u(Tk + SWZ(npp*16 + 8 + l7, ksp*4 + lg3));
            LDSM_X4(b0,b1,b2,b3, ad2);
            MMA_F16(c1[0],c1[1],c1[2],c1[3], qa[2*ksp  ][0],qa[2*ksp  ][1],qa[2*ksp  ][2],qa[2*ksp  ][3], b0,b1);
            MMA_F16(c1[0],c1[1],c1[2],c1[3], qa[2*ksp+1][0],qa[2*ksp+1][1],qa[2*ksp+1][2],qa[2*ksp+1][3], b2,b3);
        }
        __half2 h0 = __floats2half2_rn(c0[0], c0[1]);
        __half2 h1 = __floats2half2_rn(c0[2], c0[3]);
        __half2 h2 = __floats2half2_rn(c1[0], c1[1]);
        __half2 h3 = __floats2half2_rn(c1[2], c1[3]);
        uint32_t sad = s2u(SrelH + (rw + l15)*SRS + pbS + npp*16 + lq16);
        STSM_X4(sad, h2u(h0), h2u(h1), h2u(h2), h2u(h3));
    }
}

__global__ __launch_bounds__(128, 2) void attn_kernel()
{
    extern __shared__ __half smh[];
    __half* SrelH = smh;
    __half* Bw    = SrelH + 64*SRS;
    __half* KhB   = Bw    + 64*SBW;
    __half* VhB   = KhB   + 2*4096;
    __half* TkB   = VhB   + 2*4096;
    __half* TrvB  = TkB   + 2*4096;

    const int b  = blockIdx.z;
    const int h  = blockIdx.y;
    const int bx = blockIdx.x;
    const int q0 = bx * QB;
    const int tid  = threadIdx.x;
    const int warp = tid >> 5, lane = tid & 31;
    const int g = lane >> 2, t = lane & 3;
    const int l7 = lane & 7, l15 = lane & 15;
    const int lg3 = lane >> 3;
    const int lq16 = (lane >> 4) << 3;
    const int tkk = ((lane >> 3) & 1) << 3;
    const int tn8 = lane >> 4;
    const int rw = warp * 16;
    const int row0 = rw + g, row1 = rw + g + 8;

    const int d00 = -q0;
    const int bb0 = -bx;

    #pragma unroll
    for (int i = 0; i < 4; i++) {
        int id = tid + i*128;
        int r = id >> 3, c8 = id & 7, c = c8 << 3;
        CP16(s2u(Bw + r*SBW + c),
             g_qh + (((size_t)((b*LL + q0 + r)*HH + h)) << 6) + c);
        CP16(s2u(KhB + SWZ(r, c8)),
             g_kh + (((size_t)((b*LL + r)*HH + h)) << 6) + c);
        CP16(s2u(VhB + SWZ(r, c8)),
             g_vh + (((size_t)((b*LL + r)*HH + h)) << 6) + c);
        int dfc = clampdiff(d00 + r);
        CP16(s2u(TkB + SWZ(r, c8)),
             g_relk_h + ((size_t)(dfc + MAXREL) << 6) + c);
        int dfh = clampdiff(d00 - 64 + r);
        CP16(s2u(TkB + 4096 + SWZ(r, c8)),
             g_relk_h + ((size_t)(dfh + MAXREL) << 6) + c);
        CP16(s2u(TrvB + m3(bb0-1)*4096 + SWZ(r, c8)),
             g_relv_h + ((size_t)(dfh + MAXREL) << 6) + c);
        CP16(s2u(TrvB + m3(bb0)*4096 + SWZ(r, c8)),
             g_relv_h + ((size_t)(dfc + MAXREL) << 6) + c);
    }
    CPCOMMIT(); CPWAITALL();
    __syncthreads();

    uint32_t qa[4][4];
    #pragma unroll
    for (int ks = 0; ks < 4; ks++) {
        uint32_t ad = s2u(Bw + (rw + l15)*SBW + ks*16 + lq16);
        LDSM_X4(qa[ks][0], qa[ks][1], qa[ks][2], qa[ks][3], ad);
    }
    __syncthreads();

    for (int i = tid; i < 64*SBW/8; i += 128) ((uint4*)Bw)[i] = make_uint4(0,0,0,0);

    srel_block_gemm(TkB + 4096, SrelH, qa, rw, m3(bb0-1)*64, lane);
    __syncthreads();

    float oacc[8][4] = {};
    float l0 = 0.f, l1 = 0.f;

    for (int kt = 0; kt < 16; kt++) {
        const int k0 = kt * 64;
        const int d0 = k0 - q0;
        const int bb = kt - bx;
        const int cs = kt & 1, ns = cs ^ 1;

        unsigned long long bits0 = g_maskb[((size_t)(b*LL + q0 + row0) << 4) + kt];
        unsigned long long bits1 = g_maskb[((size_t)(b*LL + q0 + row1) << 4) + kt];

        if (kt < 15) {
            const int k0n = k0 + 64;
            const int trvS = m3(bb + 1)*4096;
            #pragma unroll
            for (int i = 0; i < 4; i++) {
                int id = tid + i*128;
                int r = id >> 3, c8 = id & 7, c = c8 << 3;
                CP16(s2u(KhB + ns*4096 + SWZ(r, c8)),
                     g_kh + (((size_t)((b*LL + k0n + r)*HH + h)) << 6) + c);
                CP16(s2u(VhB + ns*4096 + SWZ(r, c8)),
                     g_vh + (((size_t)((b*LL + k0n + r)*HH + h)) << 6) + c);
                int df = clampdiff(d0 + 64 + r);
                CP16(s2u(TkB + ns*4096 + SWZ(r, c8)),
                     g_relk_h + ((size_t)(df + MAXREL) << 6) + c);
                CP16(s2u(TrvB + trvS + SWZ(r, c8)),
                     g_relv_h + ((size_t)(df + MAXREL) << 6) + c);
            }
            CPCOMMIT();
        }

        float s[8][4] = {};
        #pragma unroll
        for (int np = 0; np < 8; np++) {
            #pragma unroll
            for (int ksp = 0; ksp < 2; ksp++) {
                uint32_t b0,b1,b2,b3;
                uint32_t ad = s2u(KhB + cs*4096 + SWZ(np*8 + l7, ksp*4 + lg3));
                LDSM_X4(b0,b1,b2,b3, ad);
                MMA_F16(s[np][0],s[np][1],s[np][2],s[np][3],
                        qa[2*ksp  ][0],qa[2*ksp  ][1],qa[2*ksp  ][2],qa[2*ksp  ][3], b0,b1);
                MMA_F16(s[np][0],s[np][1],s[np][2],s[np][3],
                        qa[2*ksp+1][0],qa[2*ksp+1][1],qa[2*ksp+1][2],qa[2*ksp+1][3], b2,b3);
            }
        }
        srel_block_gemm(TkB + cs*4096, SrelH, qa, rw, m3(bb)*64, lane);
        __syncwarp();

        {
            const int sLo = m3(bb - 1)*64, sHi = m3(bb)*64;
            const __half* pA0 = SrelH + row0*SRS + sLo + 64 - row0;
            const __half* pB0 = SrelH + row0*SRS + sHi - row0;
            const __half* pA1 = SrelH + row1*SRS + sLo + 64 - row1;
            const __half* pB1 = SrelH + row1*SRS + sHi - row1;
            float ls0 = 0.f, ls1 = 0.f;
            #pragma unroll
            for (int np = 0; np < 8; np++) {
                #pragma unroll
                for (int i = 0; i < 2; i++) {
                    const int c = np*8 + 2*t + i;
                    float rel0 = __half2float((c < row0) ? pA0[c] : pB0[c]);
                    float rel1 = __half2float((c < row1) ? pA1[c] : pB1[c]);
                    float v0 = ((bits0 >> c) & 1ull) ? s[np][i]     : NEGBIG;
                    float v1 = ((bits1 >> c) & 1ull) ? s[np][2 + i] : NEGBIG;
                    float p0 = __expf(v0 + rel0);
                    float p1 = __expf(v1 + rel1);
                    s[np][i] = p0;  s[np][2 + i] = p1;
                    ls0 += p0;      ls1 += p1;
                }
            }
            ls0 += __shfl_xor_sync(0xffffffffu, ls0, 1);
            ls0 += __shfl_xor_sync(0xffffffffu, ls0, 2);
            ls1 += __shfl_xor_sync(0xffffffffu, ls1, 1);
            ls1 += __shfl_xor_sync(0xffffffffu, ls1, 2);
            l0 += ls0;  l1 += ls1;
        }

        uint32_t pa[4][4];
        #pragma unroll
        for (int ks = 0; ks < 4; ks++) {
            pa[ks][0] = h2u(__floats2half2_rn(s[2*ks  ][0], s[2*ks  ][1]));
            pa[ks][1] = h2u(__floats2half2_rn(s[2*ks  ][2], s[2*ks  ][3]));
            pa[ks][2] = h2u(__floats2half2_rn(s[2*ks+1][0], s[2*ks+1][1]));
            pa[ks][3] = h2u(__floats2half2_rn(s[2*ks+1][2], s[2*ks+1][3]));
        }
        #pragma unroll
        for (int np = 0; np < 8; np++) {
            #pragma unroll
            for (int i = 0; i < 2; i++) {
                const int c = np*8 + 2*t + i;
                Bw[row0*SBW + c - g + 15] = __float2half_rn(s[np][i]);
                Bw[row1*SBW + c - g +  7] = __float2half_rn(s[np][2 + i]);
            }
        }
        __syncwarp();

        #pragma unroll
        for (int ks = 0; ks < 4; ks++) {
            #pragma unroll
            for (int ndc = 0; ndc < 4; ndc++) {
                uint32_t b0,b1,b2,b3;
                uint32_t ad = s2u(VhB + cs*4096 + SWZ(ks*16 + tkk + l7, ndc*2 + tn8));
                LDSM_X4_T(b0,b1,b2,b3, ad);
                MMA_F16(oacc[2*ndc  ][0],oacc[2*ndc  ][1],oacc[2*ndc  ][2],oacc[2*ndc  ][3],
                        pa[ks][0],pa[ks][1],pa[ks][2],pa[ks][3], b0,b1);
                MMA_F16(oacc[2*ndc+1][0],oacc[2*ndc+1][1],oacc[2*ndc+1][2],oacc[2*ndc+1][3],
                        pa[ks][0],pa[ks][1],pa[ks][2],pa[ks][3], b2,b3);
            }
        }
        #pragma unroll
        for (int ks = 0; ks < 5; ks++) {
            uint32_t ua0,ua1,ua2,ua3;
            uint32_t aad = s2u(Bw + (rw + l15)*SBW + ks*16 + lq16);
            LDSM_X4(ua0,ua1,ua2,ua3, aad);
            int dd = d0 - 15 - rw + ks*16 + tkk + l7;
            if (dd > d0 + 63) dd = d0 + 63;
            int bdd = dd >> 6;
            int prow = m3(bdd)*64 + (dd & 63);
            #pragma unroll
            for (int ndc = 0; ndc < 4; ndc++) {
                uint32_t b0,b1,b2,b3;
                LDSM_X4_T(b0,b1,b2,b3, s2u(TrvB + SWZ(prow, ndc*2 + tn8)));
                MMA_F16(oacc[2*ndc  ][0],oacc[2*ndc  ][1],oacc[2*ndc  ][2],oacc[2*ndc  ][3],
                        ua0,ua1,ua2,ua3, b0,b1);
                MMA_F16(oacc[2*ndc+1][0],oacc[2*ndc+1][1],oacc[2*ndc+1][2],oacc[2*ndc+1][3],
                        ua0,ua1,ua2,ua3, b2,b3);
            }
        }

        CPWAITALL();
        __syncthreads();
    }

    {
        const float inv0 = 1.0f / l0;
        const float inv1 = 1.0f / l1;
        const size_t base0 = (((size_t)((b*LL + q0 + row0)*HH + h)) << 6);
        const size_t base1 = (((size_t)((b*LL + q0 + row1)*HH + h)) << 6);
        #pragma unroll
        for (int np = 0; np < 8; np++) {
            const int c = np*8 + 2*t;
            __half2 h0 = __floats2half2_rn(oacc[np][0]*inv0, oacc[np][1]*inv0);
            __half2 h1 = __floats2half2_rn(oacc[np][2]*inv1, oacc[np][3]*inv1);
            *(uint32_t*)(g_ctx + base0 + c) = h2u(h0);
            *(uint32_t*)(g_ctx + base1 + c) = h2u(h1);
        }
    }
}

// ---------------------------------------------------------------------------
// Final FC: 128x128 tiles, 512 threads, 2 CTAs/SM, cp.async double-buffered.
// ---------------------------------------------------------------------------
#define FCB 8192   // halves per buffer per array (128 x 64)
#define FC_SMEM_BYTES (4*FCB*2)

__global__ __launch_bounds__(512, 2) void fc_kernel(
    const float* __restrict__ bfc, float* __restrict__ out)
{
    extern __shared__ __half fcsm[];
    __half* Xs[2] = {fcsm,           fcsm + FCB};
    __half* Ws[2] = {fcsm + 2*FCB,   fcsm + 3*FCB};

    const int tid  = threadIdx.x;
    const int warp = tid >> 5, lane = tid & 31;
    const int g = lane >> 2, t = lane & 3;
    const int wr = warp >> 2, wc = warp & 3;
    const int l7 = lane & 7, l15 = lane & 15;
    const int lg3 = lane >> 3;
    const int ln16 = lane >> 4;
    const size_t r0 = (size_t)blockIdx.x * 128;
    const size_t n0 = (size_t)blockIdx.y * 128;

    float oacc[2][4][4] = {};

    // stage e = 0 into buffer 0
    #pragma unroll
    for (int i = 0; i < 2; i++) {
        int id = tid + i*512;
        int r = id >> 3, c8 = id & 7, c = c8 << 3;
        CP16(s2u(Xs[0] + SWZ(r, c8)), g_ctx   + (r0 + r)*EMBN + c);
        CP16(s2u(Ws[0] + SWZ(r, c8)), g_Wfc_h + (n0 + r)*EMBN + c);
    }
    CPCOMMIT();

    for (int e = 0; e < 16; e++) {
        const int cs = e & 1, ns = cs ^ 1;
        if (e < 15) {
            const int e0n = (e + 1) * 64;
            #pragma unroll
            for (int i = 0; i < 2; i++) {
                int id = tid + i*512;
                int r = id >> 3, c8 = id & 7, c = c8 << 3;
                CP16(s2u(Xs[ns] + SWZ(r, c8)), g_ctx   + (r0 + r)*EMBN + e0n + c);
                CP16(s2u(Ws[ns] + SWZ(r, c8)), g_Wfc_h + (n0 + r)*EMBN + e0n + c);
            }
            CPCOMMIT();
            CPWAIT1();
        } else {
            CPWAITALL();
        }
        __syncthreads();

        #pragma unroll
        for (int ksp = 0; ksp < 2; ksp++) {
            uint32_t a[2][2][4];
            #pragma unroll
            for (int mi = 0; mi < 2; mi++)
                #pragma unroll
                for (int kk = 0; kk < 2; kk++) {
                    uint32_t ad = s2u(Xs[cs] + SWZ(wr*32 + mi*16 + l15, (2*ksp + kk)*2 + ln16));
                    LDSM_X4(a[mi][kk][0], a[mi][kk][1], a[mi][kk][2], a[mi][kk][3], ad);
                }
            #pragma unroll
            for (int nt = 0; nt < 4; nt++) {
                uint32_t b0,b1,b2,b3;
                uint32_t ad = s2u(Ws[cs] + SWZ(wc*32 + nt*8 + l7, ksp*4 + lg3));
                LDSM_X4(b0,b1,b2,b3, ad);
                #pragma unroll
                for (int mi = 0; mi < 2; mi++) {
                    MMA_F16(oacc[mi][nt][0], oacc[mi][nt][1], oacc[mi][nt][2], oacc[mi][nt][3],
                            a[mi][0][0], a[mi][0][1], a[mi][0][2], a[mi][0][3], b0, b1);
                    MMA_F16(oacc[mi][nt][0], oacc[mi][nt][1], oacc[mi][nt][2], oacc[mi][nt][3],
                            a[mi][1][0], a[mi][1][1], a[mi][1][2], a[mi][1][3], b2, b3);
                }
            }
        }
        __syncthreads();
    }

    #pragma unroll
    for (int mi = 0; mi < 2; mi++) {
        size_t ra = r0 + wr*32 + mi*16 + g;
        #pragma unroll
        for (int nt = 0; nt < 4; nt++) {
            size_t c = n0 + wc*32 + nt*8 + 2*t;
            float bv0 = bfc[c], bv1 = bfc[c+1];
            *(float2*)(out + ra*EMBN + c) =
                make_float2(oacc[mi][nt][0] + bv0, oacc[mi][nt][1] + bv1);
            *(float2*)(out + (ra+8)*EMBN + c) =
                make_float2(oacc[mi][nt][2] + bv0, oacc[mi][nt][3] + bv1);
        }
    }
}

// ---------------------------------------------------------------------------
extern "C" void kernel_launch(void* const* d_in, const int* in_sizes, int n_in,
                              void* d_out, int out_size)
{
    const float* query = (const float*)d_in[0];
    const float* key_  = (const float*)d_in[1];
    const float* value = (const float*)d_in[2];
    const int*   mask  = (const int*)d_in[3];
    const float* Wq = (const float*)d_in[4];
    const float* bq = (const float*)d_in[5];
    const float* Wk = (const float*)d_in[6];
    const float* bk = (const float*)d_in[7];
    const float* Wv = (const float*)d_in[8];
    const float* bv = (const float*)d_in[9];
    const float* Wfc = (const float*)d_in[10];
    const float* bfc = (const float*)d_in[11];
    const float* relk = (const float*)d_in[12];
    const float* relv = (const float*)d_in[13];
    float* out = (float*)d_out;

    cudaFuncSetAttribute(pre_kernel,  cudaFuncAttributeMaxDynamicSharedMemorySize, PRE_SMEM_BYTES);
    cudaFuncSetAttribute(attn_kernel, cudaFuncAttributeMaxDynamicSharedMemorySize, ATT_SMEM_BYTES);
    cudaFuncSetAttribute(fc_kernel,   cudaFuncAttributeMaxDynamicSharedMemorySize, FC_SMEM_BYTES);

    pre_kernel<<<dim3(1024, 2, 1), 256, PRE_SMEM_BYTES>>>(query, key_, value, Wq, bq, Wk, bk, Wv, bv,
                                                          relk, relv, Wfc, mask);
    attn_kernel<<<dim3(LL/QB, HH, BB), 128, ATT_SMEM_BYTES>>>();
    fc_kernel<<<dim3(32, 8, 1), 512, FC_SMEM_BYTES>>>(bfc, out);
}

// round 15
// speedup vs baseline: 1.2106x; 1.0288x over previous
#include <cuda_runtime.h>
#include <cuda_fp16.h>
#include <cstdint>
#include <cstddef>

#define BB   4
#define LL   1024
#define HH   16
#define DD   64
#define EMBN 1024
#define MAXREL 512
#define NREL (2*MAXREL + 1)

#define QB   64
#define SH   72    // half stride (pre smem)
#define SRS  200   // Srel ring stride: 192 slots + pad (100 words == 4 mod 32)
#define SBW  88    // band/Q buffer stride (44 words == 12 mod 32)
#define NEGBIG (-1.25e19f)

// swizzled stride-64 tile: element (row, col8-group)
#define SWZ(r,c8) (((r) << 6) + ((((c8) ^ ((r) & 7))) << 3))

// Scratch (allocation-free rule: device globals)
__device__ __half g_qh [BB*LL*HH*DD];
__device__ __half g_kh [BB*LL*HH*DD];
__device__ __half g_vh [BB*LL*HH*DD];
__device__ __half g_ctx[BB*LL*HH*DD];
__device__ __half g_relk_h[NREL*DD];
__device__ __half g_relv_h[NREL*DD];
__device__ __half g_Wfc_h[EMBN*EMBN];
__device__ unsigned long long g_maskb[BB*LL*16];   // 64 k-bits per (row, k-tile)

// ---------------------------------------------------------------------------
#define MMA_F16(d0,d1,d2,d3,a0,a1,a2,a3,b0,b1)                               \
    asm volatile("mma.sync.aligned.m16n8k16.row.col.f32.f16.f16.f32 "        \
                 "{%0,%1,%2,%3}, {%4,%5,%6,%7}, {%8,%9}, {%0,%1,%2,%3};"     \
                 : "+f"(d0), "+f"(d1), "+f"(d2), "+f"(d3)                    \
                 : "r"(a0), "r"(a1), "r"(a2), "r"(a3), "r"(b0), "r"(b1))

#define LDSM_X4(r0,r1,r2,r3,addr)                                            \
    asm volatile("ldmatrix.sync.aligned.m8n8.x4.shared.b16 {%0,%1,%2,%3}, [%4];" \
                 : "=r"(r0), "=r"(r1), "=r"(r2), "=r"(r3) : "r"(addr) : "memory")

#define LDSM_X4_T(r0,r1,r2,r3,addr)                                          \
    asm volatile("ldmatrix.sync.aligned.m8n8.x4.trans.shared.b16 {%0,%1,%2,%3}, [%4];" \
                 : "=r"(r0), "=r"(r1), "=r"(r2), "=r"(r3) : "r"(addr) : "memory")

#define STSM_X4(addr,r0,r1,r2,r3)                                            \
    asm volatile("stmatrix.sync.aligned.m8n8.x4.shared.b16 [%0], {%1,%2,%3,%4};" \
                 :: "r"(addr), "r"(r0), "r"(r1), "r"(r2), "r"(r3) : "memory")

#define CP16(dst,src)                                                        \
    asm volatile("cp.async.cg.shared.global [%0], [%1], 16;" :: "r"(dst), "l"(src))
#define CPCOMMIT()  asm volatile("cp.async.commit_group;")
#define CPWAITALL() asm volatile("cp.async.wait_group 0;" ::: "memory")
#define CPWAIT1()   asm volatile("cp.async.wait_group 1;" ::: "memory")

__device__ __forceinline__ uint32_t ldh2(const __half* p) { return *(const uint32_t*)p; }
__device__ __forceinline__ uint32_t s2u(const void* p) {
    return (uint32_t)__cvta_generic_to_shared(p);
}
__device__ __forceinline__ int clampdiff(int d) {
    return d < -MAXREL ? -MAXREL : (d > MAXREL ? MAXREL : d);
}
__device__ __forceinline__ int m3(int x) { return (x + 48) % 3; }   // x >= -48
__device__ __forceinline__ uint2 f4_to_h4(float4 v) {
    __half2 h0 = __floats2half2_rn(v.x, v.y);
    __half2 h1 = __floats2half2_rn(v.z, v.w);
    uint2 r; r.x = *(uint32_t*)&h0; r.y = *(uint32_t*)&h1; return r;
}
__device__ __forceinline__ uint32_t h2u(__half2 h) { return *(uint32_t*)&h; }

// ---------------------------------------------------------------------------
// Pre: projections via fp16 mma (y=0..2; Q pre-scaled 0.125) + constants (y=3)
// (round-13 version: light CTAs, high occupancy)
// ---------------------------------------------------------------------------
__global__ __launch_bounds__(256) void pre_kernel(
    const float* __restrict__ query, const float* __restrict__ key_, const float* __restrict__ value,
    const float* __restrict__ Wq, const float* __restrict__ bq,
    const float* __restrict__ Wk, const float* __restrict__ bk,
    const float* __restrict__ Wv, const float* __restrict__ bv,
    const float* __restrict__ relk, const float* __restrict__ relv,
    const float* __restrict__ Wfc,  const int* __restrict__ mask)
{
    const int tid = threadIdx.x;

    if (blockIdx.y == 3) {
        const int stride = 1024 * 256;
        const int base = blockIdx.x * 256 + tid;
        for (int i = base; i < NREL*DD/4; i += stride) {
            float4 a = *(const float4*)(relk + (size_t)i*4);
            float4 b = *(const float4*)(relv + (size_t)i*4);
            *(uint2*)(g_relk_h + (size_t)i*4) = f4_to_h4(a);
            *(uint2*)(g_relv_h + (size_t)i*4) = f4_to_h4(b);
        }
        for (int i = base; i < EMBN*EMBN/4; i += stride) {
            float4 w = *(const float4*)(Wfc + (size_t)i*4);
            *(uint2*)(g_Wfc_h + (size_t)i*4) = f4_to_h4(w);
        }
        for (int i = base; i < BB*LL*16; i += stride) {
            int row = i >> 4, w = i & 15;
            const int* mrow = mask + (size_t)row*LL + w*64;
            unsigned long long bits = 0ull;
            #pragma unroll
            for (int j = 0; j < 16; j++) {
                int4 v = *(const int4*)(mrow + j*4);
                bits |= (unsigned long long)(v.x != 0) << (4*j + 0);
                bits |= (unsigned long long)(v.y != 0) << (4*j + 1);
                bits |= (unsigned long long)(v.z != 0) << (4*j + 2);
                bits |= (unsigned long long)(v.w != 0) << (4*j + 3);
            }
            g_maskb[i] = bits;
        }
        return;
    }

    __shared__ __half Xs[64*SH];
    __shared__ __half Ws[64*SH];
    __shared__ float bs[64];

    const float* X; const float* W; const float* bias; __half* out;
    float oscale = 1.0f;
    if (blockIdx.y == 0)      { X = query; W = Wq; bias = bq; out = g_qh; oscale = 0.125f; }
    else if (blockIdx.y == 1) { X = key_;  W = Wk; bias = bk; out = g_kh; }
    else                      { X = value; W = Wv; bias = bv; out = g_vh; }

    const size_t r0 = (size_t)blockIdx.x * 64;
    const int warp = tid >> 5, lane = tid & 31;
    const int g = lane >> 2, t = lane & 3;
    const int wr = warp >> 2, wc = warp & 3;
    const int l7 = lane & 7, l15 = lane & 15;
    const int lq8 = (lane >> 3) << 3;
    const int lq16 = (lane >> 4) << 3;

    {
        const int rr = tid >> 2, cb = (tid & 3) << 4;
        #pragma unroll
        for (int i = 0; i < 4; i++) {
            float4 v = *(const float4*)(X + (r0 + rr)*64 + cb + i*4);
            *(uint2*)&Xs[rr*SH + cb + i*4] = f4_to_h4(v);
            float4 w = *(const float4*)(W + (size_t)rr*64 + cb + i*4);
            *(uint2*)&Ws[rr*SH + cb + i*4] = f4_to_h4(w);
        }
    }
    if (tid < 64) bs[tid] = bias[tid];
    __syncthreads();

    uint32_t qa[2][4][4];
    #pragma unroll
    for (int mt = 0; mt < 2; mt++)
        #pragma unroll
        for (int ks = 0; ks < 4; ks++) {
            uint32_t ad = s2u(Xs + (wr*32 + mt*16 + l15)*SH + ks*16 + lq16);
            LDSM_X4(qa[mt][ks][0], qa[mt][ks][1], qa[mt][ks][2], qa[mt][ks][3], ad);
        }

    #pragma unroll
    for (int nt = 0; nt < 2; nt++) {
        float c0[4] = {0,0,0,0}, c1[4] = {0,0,0,0};
        #pragma unroll
        for (int ksp = 0; ksp < 2; ksp++) {
            uint32_t b0,b1,b2,b3;
            uint32_t ad = s2u(Ws + (wc*16 + nt*8 + l7)*SH + ksp*32 + lq8);
            LDSM_X4(b0,b1,b2,b3, ad);
            MMA_F16(c0[0],c0[1],c0[2],c0[3], qa[0][2*ksp  ][0],qa[0][2*ksp  ][1],qa[0][2*ksp  ][2],qa[0][2*ksp  ][3], b0,b1);
            MMA_F16(c1[0],c1[1],c1[2],c1[3], qa[1][2*ksp  ][0],qa[1][2*ksp  ][1],qa[1][2*ksp  ][2],qa[1][2*ksp  ][3], b0,b1);
            MMA_F16(c0[0],c0[1],c0[2],c0[3], qa[0][2*ksp+1][0],qa[0][2*ksp+1][1],qa[0][2*ksp+1][2],qa[0][2*ksp+1][3], b2,b3);
            MMA_F16(c1[0],c1[1],c1[2],c1[3], qa[1][2*ksp+1][0],qa[1][2*ksp+1][1],qa[1][2*ksp+1][2],qa[1][2*ksp+1][3], b2,b3);
        }
        const int cb2 = wc*16 + nt*8 + 2*t;
        const float bv0 = bs[cb2], bv1 = bs[cb2 + 1];
        __half2 h00 = __floats2half2_rn((c0[0] + bv0)*oscale, (c0[1] + bv1)*oscale);
        __half2 h01 = __floats2half2_rn((c0[2] + bv0)*oscale, (c0[3] + bv1)*oscale);
        __half2 h10 = __floats2half2_rn((c1[0] + bv0)*oscale, (c1[1] + bv1)*oscale);
        __half2 h11 = __floats2half2_rn((c1[2] + bv0)*oscale, (c1[3] + bv1)*oscale);
        *(uint32_t*)(out + (r0 + wr*32      + g)*64 + cb2) = h2u(h00);
        *(uint32_t*)(out + (r0 + wr*32 +  8 + g)*64 + cb2) = h2u(h01);
        *(uint32_t*)(out + (r0 + wr*32 + 16 + g)*64 + cb2) = h2u(h10);
        *(uint32_t*)(out + (r0 + wr*32 + 24 + g)*64 + cb2) = h2u(h11);
    }
}

// ---------------------------------------------------------------------------
// Attention (round-13): QB=64, 4 warps, 2 CTAs/SM, swizzled tiles, mod-3 rings.
// ---------------------------------------------------------------------------
#define ATT_SMEM_HALFS (64*SRS + 64*SBW + 9*4096)
#define ATT_SMEM_BYTES (ATT_SMEM_HALFS*2)

__device__ __forceinline__ void srel_block_gemm(
    const __half* Tk, __half* SrelH, const uint32_t qa[4][4],
    int rw, int pbS, int lane)
{
    const int l7 = lane & 7, l15 = lane & 15;
    const int lg3 = lane >> 3;
    const int lq16 = (lane >> 4) << 3;
    #pragma unroll
    for (int npp = 0; npp < 4; npp++) {
        float c0[4] = {0,0,0,0}, c1[4] = {0,0,0,0};
        #pragma unroll
        for (int ksp = 0; ksp < 2; ksp++) {
            uint32_t b0,b1,b2,b3;
            uint32_t ad = s2u(Tk + SWZ(npp*16 + l7, ksp*4 + lg3));
            LDSM_X4(b0,b1,b2,b3, ad);
            MMA_F16(c0[0],c0[1],c0[2],c0[3], qa[2*ksp  ][0],qa[2*ksp  ][1],qa[2*ksp  ][2],qa[2*ksp  ][3], b0,b1);
            MMA_F16(c0[0],c0[1],c0[2],c0[3], qa[2*ksp+1][0],qa[2*ksp+1][1],qa[2*ksp+1][2],qa[2*ksp+1][3], b2,b3);
            uint32_t ad2 = s2u(Tk + SWZ(npp*16 + 8 + l7, ksp*4 + lg3));
            LDSM_X4(b0,b1,b2,b3, ad2);
            MMA_F16(c1[0],c1[1],c1[2],c1[3], qa[2*ksp  ][0],qa[2*ksp  ][1],qa[2*ksp  ][2],qa[2*ksp  ][3], b0,b1);
            MMA_F16(c1[0],c1[1],c1[2],c1[3], qa[2*ksp+1][0],qa[2*ksp+1][1],qa[2*ksp+1][2],qa[2*ksp+1][3], b2,b3);
        }
        __half2 h0 = __floats2half2_rn(c0[0], c0[1]);
        __half2 h1 = __floats2half2_rn(c0[2], c0[3]);
        __half2 h2 = __floats2half2_rn(c1[0], c1[1]);
        __half2 h3 = __floats2half2_rn(c1[2], c1[3]);
        uint32_t sad = s2u(SrelH + (rw + l15)*SRS + pbS + npp*16 + lq16);
        STSM_X4(sad, h2u(h0), h2u(h1), h2u(h2), h2u(h3));
    }
}

__global__ __launch_bounds__(128, 2) void attn_kernel()
{
    extern __shared__ __half smh[];
    __half* SrelH = smh;
    __half* Bw    = SrelH + 64*SRS;
    __half* KhB   = Bw    + 64*SBW;
    __half* VhB   = KhB   + 2*4096;
    __half* TkB   = VhB   + 2*4096;
    __half* TrvB  = TkB   + 2*4096;

    const int b  = blockIdx.z;
    const int h  = blockIdx.y;
    const int bx = blockIdx.x;
    const int q0 = bx * QB;
    const int tid  = threadIdx.x;
    const int warp = tid >> 5, lane = tid & 31;
    const int g = lane >> 2, t = lane & 3;
    const int l7 = lane & 7, l15 = lane & 15;
    const int lg3 = lane >> 3;
    const int lq16 = (lane >> 4) << 3;
    const int tkk = ((lane >> 3) & 1) << 3;
    const int tn8 = lane >> 4;
    const int rw = warp * 16;
    const int row0 = rw + g, row1 = rw + g + 8;

    const int d00 = -q0;
    const int bb0 = -bx;

    #pragma unroll
    for (int i = 0; i < 4; i++) {
        int id = tid + i*128;
        int r = id >> 3, c8 = id & 7, c = c8 << 3;
        CP16(s2u(Bw + r*SBW + c),
             g_qh + (((size_t)((b*LL + q0 + r)*HH + h)) << 6) + c);
        CP16(s2u(KhB + SWZ(r, c8)),
             g_kh + (((size_t)((b*LL + r)*HH + h)) << 6) + c);
        CP16(s2u(VhB + SWZ(r, c8)),
             g_vh + (((size_t)((b*LL + r)*HH + h)) << 6) + c);
        int dfc = clampdiff(d00 + r);
        CP16(s2u(TkB + SWZ(r, c8)),
             g_relk_h + ((size_t)(dfc + MAXREL) << 6) + c);
        int dfh = clampdiff(d00 - 64 + r);
        CP16(s2u(TkB + 4096 + SWZ(r, c8)),
             g_relk_h + ((size_t)(dfh + MAXREL) << 6) + c);
        CP16(s2u(TrvB + m3(bb0-1)*4096 + SWZ(r, c8)),
             g_relv_h + ((size_t)(dfh + MAXREL) << 6) + c);
        CP16(s2u(TrvB + m3(bb0)*4096 + SWZ(r, c8)),
             g_relv_h + ((size_t)(dfc + MAXREL) << 6) + c);
    }
    CPCOMMIT(); CPWAITALL();
    __syncthreads();

    uint32_t qa[4][4];
    #pragma unroll
    for (int ks = 0; ks < 4; ks++) {
        uint32_t ad = s2u(Bw + (rw + l15)*SBW + ks*16 + lq16);
        LDSM_X4(qa[ks][0], qa[ks][1], qa[ks][2], qa[ks][3], ad);
    }
    __syncthreads();

    for (int i = tid; i < 64*SBW/8; i += 128) ((uint4*)Bw)[i] = make_uint4(0,0,0,0);

    srel_block_gemm(TkB + 4096, SrelH, qa, rw, m3(bb0-1)*64, lane);
    __syncthreads();

    float oacc[8][4] = {};
    float l0 = 0.f, l1 = 0.f;

    for (int kt = 0; kt < 16; kt++) {
        const int k0 = kt * 64;
        const int d0 = k0 - q0;
        const int bb = kt - bx;
        const int cs = kt & 1, ns = cs ^ 1;

        unsigned long long bits0 = g_maskb[((size_t)(b*LL + q0 + row0) << 4) + kt];
        unsigned long long bits1 = g_maskb[((size_t)(b*LL + q0 + row1) << 4) + kt];

        if (kt < 15) {
            const int k0n = k0 + 64;
            const int trvS = m3(bb + 1)*4096;
            #pragma unroll
            for (int i = 0; i < 4; i++) {
                int id = tid + i*128;
                int r = id >> 3, c8 = id & 7, c = c8 << 3;
                CP16(s2u(KhB + ns*4096 + SWZ(r, c8)),
                     g_kh + (((size_t)((b*LL + k0n + r)*HH + h)) << 6) + c);
                CP16(s2u(VhB + ns*4096 + SWZ(r, c8)),
                     g_vh + (((size_t)((b*LL + k0n + r)*HH + h)) << 6) + c);
                int df = clampdiff(d0 + 64 + r);
                CP16(s2u(TkB + ns*4096 + SWZ(r, c8)),
                     g_relk_h + ((size_t)(df + MAXREL) << 6) + c);
                CP16(s2u(TrvB + trvS + SWZ(r, c8)),
                     g_relv_h + ((size_t)(df + MAXREL) << 6) + c);
            }
            CPCOMMIT();
        }

        float s[8][4] = {};
        #pragma unroll
        for (int np = 0; np < 8; np++) {
            #pragma unroll
            for (int ksp = 0; ksp < 2; ksp++) {
                uint32_t b0,b1,b2,b3;
                uint32_t ad = s2u(KhB + cs*4096 + SWZ(np*8 + l7, ksp*4 + lg3));
                LDSM_X4(b0,b1,b2,b3, ad);
                MMA_F16(s[np][0],s[np][1],s[np][2],s[np][3],
                        qa[2*ksp  ][0],qa[2*ksp  ][1],qa[2*ksp  ][2],qa[2*ksp  ][3], b0,b1);
                MMA_F16(s[np][0],s[np][1],s[np][2],s[np][3],
                        qa[2*ksp+1][0],qa[2*ksp+1][1],qa[2*ksp+1][2],qa[2*ksp+1][3], b2,b3);
            }
        }
        srel_block_gemm(TkB + cs*4096, SrelH, qa, rw, m3(bb)*64, lane);
        __syncwarp();

        {
            const int sLo = m3(bb - 1)*64, sHi = m3(bb)*64;
            const __half* pA0 = SrelH + row0*SRS + sLo + 64 - row0;
            const __half* pB0 = SrelH + row0*SRS + sHi - row0;
            const __half* pA1 = SrelH + row1*SRS + sLo + 64 - row1;
            const __half* pB1 = SrelH + row1*SRS + sHi - row1;
            float ls0 = 0.f, ls1 = 0.f;
            #pragma unroll
            for (int np = 0; np < 8; np++) {
                #pragma unroll
                for (int i = 0; i < 2; i++) {
                    const int c = np*8 + 2*t + i;
                    float rel0 = __half2float((c < row0) ? pA0[c] : pB0[c]);
                    float rel1 = __half2float((c < row1) ? pA1[c] : pB1[c]);
                    float v0 = ((bits0 >> c) & 1ull) ? s[np][i]     : NEGBIG;
                    float v1 = ((bits1 >> c) & 1ull) ? s[np][2 + i] : NEGBIG;
                    float p0 = __expf(v0 + rel0);
                    float p1 = __expf(v1 + rel1);
                    s[np][i] = p0;  s[np][2 + i] = p1;
                    ls0 += p0;      ls1 += p1;
                }
            }
            ls0 += __shfl_xor_sync(0xffffffffu, ls0, 1);
            ls0 += __shfl_xor_sync(0xffffffffu, ls0, 2);
            ls1 += __shfl_xor_sync(0xffffffffu, ls1, 1);
            ls1 += __shfl_xor_sync(0xffffffffu, ls1, 2);
            l0 += ls0;  l1 += ls1;
        }

        uint32_t pa[4][4];
        #pragma unroll
        for (int ks = 0; ks < 4; ks++) {
            pa[ks][0] = h2u(__floats2half2_rn(s[2*ks  ][0], s[2*ks  ][1]));
            pa[ks][1] = h2u(__floats2half2_rn(s[2*ks  ][2], s[2*ks  ][3]));
            pa[ks][2] = h2u(__floats2half2_rn(s[2*ks+1][0], s[2*ks+1][1]));
            pa[ks][3] = h2u(__floats2half2_rn(s[2*ks+1][2], s[2*ks+1][3]));
        }
        #pragma unroll
        for (int np = 0; np < 8; np++) {
            #pragma unroll
            for (int i = 0; i < 2; i++) {
                const int c = np*8 + 2*t + i;
                Bw[row0*SBW + c - g + 15] = __float2half_rn(s[np][i]);
                Bw[row1*SBW + c - g +  7] = __float2half_rn(s[np][2 + i]);
            }
        }
        __syncwarp();

        #pragma unroll
        for (int ks = 0; ks < 4; ks++) {
            #pragma unroll
            for (int ndc = 0; ndc < 4; ndc++) {
                uint32_t b0,b1,b2,b3;
                uint32_t ad = s2u(VhB + cs*4096 + SWZ(ks*16 + tkk + l7, ndc*2 + tn8));
                LDSM_X4_T(b0,b1,b2,b3, ad);
                MMA_F16(oacc[2*ndc  ][0],oacc[2*ndc  ][1],oacc[2*ndc  ][2],oacc[2*ndc  ][3],
                        pa[ks][0],pa[ks][1],pa[ks][2],pa[ks][3], b0,b1);
                MMA_F16(oacc[2*ndc+1][0],oacc[2*ndc+1][1],oacc[2*ndc+1][2],oacc[2*ndc+1][3],
                        pa[ks][0],pa[ks][1],pa[ks][2],pa[ks][3], b2,b3);
            }
        }
        #pragma unroll
        for (int ks = 0; ks < 5; ks++) {
            uint32_t ua0,ua1,ua2,ua3;
            uint32_t aad = s2u(Bw + (rw + l15)*SBW + ks*16 + lq16);
            LDSM_X4(ua0,ua1,ua2,ua3, aad);
            int dd = d0 - 15 - rw + ks*16 + tkk + l7;
            if (dd > d0 + 63) dd = d0 + 63;
            int bdd = dd >> 6;
            int prow = m3(bdd)*64 + (dd & 63);
            #pragma unroll
            for (int ndc = 0; ndc < 4; ndc++) {
                uint32_t b0,b1,b2,b3;
                LDSM_X4_T(b0,b1,b2,b3, s2u(TrvB + SWZ(prow, ndc*2 + tn8)));
                MMA_F16(oacc[2*ndc  ][0],oacc[2*ndc  ][1],oacc[2*ndc  ][2],oacc[2*ndc  ][3],
                        ua0,ua1,ua2,ua3, b0,b1);
                MMA_F16(oacc[2*ndc+1][0],oacc[2*ndc+1][1],oacc[2*ndc+1][2],oacc[2*ndc+1][3],
                        ua0,ua1,ua2,ua3, b2,b3);
            }
        }

        CPWAITALL();
        __syncthreads();
    }

    {
        const float inv0 = 1.0f / l0;
        const float inv1 = 1.0f / l1;
        const size_t base0 = (((size_t)((b*LL + q0 + row0)*HH + h)) << 6);
        const size_t base1 = (((size_t)((b*LL + q0 + row1)*HH + h)) << 6);
        #pragma unroll
        for (int np = 0; np < 8; np++) {
            const int c = np*8 + 2*t;
            __half2 h0 = __floats2half2_rn(oacc[np][0]*inv0, oacc[np][1]*inv0);
            __half2 h1 = __floats2half2_rn(oacc[np][2]*inv1, oacc[np][3]*inv1);
            *(uint32_t*)(g_ctx + base0 + c) = h2u(h0);
            *(uint32_t*)(g_ctx + base1 + c) = h2u(h1);
        }
    }
}

// ---------------------------------------------------------------------------
// Final FC: 128x128 tiles, 512 threads, 2 CTAs/SM, cp.async double-buffered.
// ---------------------------------------------------------------------------
#define FCB 8192   // halves per buffer per array (128 x 64)
#define FC_SMEM_BYTES (4*FCB*2)

__global__ __launch_bounds__(512, 2) void fc_kernel(
    const float* __restrict__ bfc, float* __restrict__ out)
{
    extern __shared__ __half fcsm[];
    __half* Xs[2] = {fcsm,           fcsm + FCB};
    __half* Ws[2] = {fcsm + 2*FCB,   fcsm + 3*FCB};

    const int tid  = threadIdx.x;
    const int warp = tid >> 5, lane = tid & 31;
    const int g = lane >> 2, t = lane & 3;
    const int wr = warp >> 2, wc = warp & 3;
    const int l7 = lane & 7, l15 = lane & 15;
    const int lg3 = lane >> 3;
    const int ln16 = lane >> 4;
    const size_t r0 = (size_t)blockIdx.x * 128;
    const size_t n0 = (size_t)blockIdx.y * 128;

    float oacc[2][4][4] = {};

    #pragma unroll
    for (int i = 0; i < 2; i++) {
        int id = tid + i*512;
        int r = id >> 3, c8 = id & 7, c = c8 << 3;
        CP16(s2u(Xs[0] + SWZ(r, c8)), g_ctx   + (r0 + r)*EMBN + c);
        CP16(s2u(Ws[0] + SWZ(r, c8)), g_Wfc_h + (n0 + r)*EMBN + c);
    }
    CPCOMMIT();

    for (int e = 0; e < 16; e++) {
        const int cs = e & 1, ns = cs ^ 1;
        if (e < 15) {
            const int e0n = (e + 1) * 64;
            #pragma unroll
            for (int i = 0; i < 2; i++) {
                int id = tid + i*512;
                int r = id >> 3, c8 = id & 7, c = c8 << 3;
                CP16(s2u(Xs[ns] + SWZ(r, c8)), g_ctx   + (r0 + r)*EMBN + e0n + c);
                CP16(s2u(Ws[ns] + SWZ(r, c8)), g_Wfc_h + (n0 + r)*EMBN + e0n + c);
            }
            CPCOMMIT();
            CPWAIT1();
        } else {
            CPWAITALL();
        }
        __syncthreads();

        #pragma unroll
        for (int ksp = 0; ksp < 2; ksp++) {
            uint32_t a[2][2][4];
            #pragma unroll
            for (int mi = 0; mi < 2; mi++)
                #pragma unroll
                for (int kk = 0; kk < 2; kk++) {
                    uint32_t ad = s2u(Xs[cs] + SWZ(wr*32 + mi*16 + l15, (2*ksp + kk)*2 + ln16));
                    LDSM_X4(a[mi][kk][0], a[mi][kk][1], a[mi][kk][2], a[mi][kk][3], ad);
                }
            #pragma unroll
            for (int nt = 0; nt < 4; nt++) {
                uint32_t b0,b1,b2,b3;
                uint32_t ad = s2u(Ws[cs] + SWZ(wc*32 + nt*8 + l7, ksp*4 + lg3));
                LDSM_X4(b0,b1,b2,b3, ad);
                #pragma unroll
                for (int mi = 0; mi < 2; mi++) {
                    MMA_F16(oacc[mi][nt][0], oacc[mi][nt][1], oacc[mi][nt][2], oacc[mi][nt][3],
                            a[mi][0][0], a[mi][0][1], a[mi][0][2], a[mi][0][3], b0, b1);
                    MMA_F16(oacc[mi][nt][0], oacc[mi][nt][1], oacc[mi][nt][2], oacc[mi][nt][3],
                            a[mi][1][0], a[mi][1][1], a[mi][1][2], a[mi][1][3], b2, b3);
                }
            }
        }
        __syncthreads();
    }

    #pragma unroll
    for (int mi = 0; mi < 2; mi++) {
        size_t ra = r0 + wr*32 + mi*16 + g;
        #pragma unroll
        for (int nt = 0; nt < 4; nt++) {
            size_t c = n0 + wc*32 + nt*8 + 2*t;
            float bv0 = bfc[c], bv1 = bfc[c+1];
            *(float2*)(out + ra*EMBN + c) =
                make_float2(oacc[mi][nt][0] + bv0, oacc[mi][nt][1] + bv1);
            *(float2*)(out + (ra+8)*EMBN + c) =
                make_float2(oacc[mi][nt][2] + bv0, oacc[mi][nt][3] + bv1);
        }
    }
}

// ---------------------------------------------------------------------------
extern "C" void kernel_launch(void* const* d_in, const int* in_sizes, int n_in,
                              void* d_out, int out_size)
{
    const float* query = (const float*)d_in[0];
    const float* key_  = (const float*)d_in[1];
    const float* value = (const float*)d_in[2];
    const int*   mask  = (const int*)d_in[3];
    const float* Wq = (const float*)d_in[4];
    const float* bq = (const float*)d_in[5];
    const float* Wk = (const float*)d_in[6];
    const float* bk = (const float*)d_in[7];
    const float* Wv = (const float*)d_in[8];
    const float* bv = (const float*)d_in[9];
    const float* Wfc = (const float*)d_in[10];
    const float* bfc = (const float*)d_in[11];
    const float* relk = (const float*)d_in[12];
    const float* relv = (const float*)d_in[13];
    float* out = (float*)d_out;

    cudaFuncSetAttribute(attn_kernel, cudaFuncAttributeMaxDynamicSharedMemorySize, ATT_SMEM_BYTES);
    cudaFuncSetAttribute(fc_kernel,   cudaFuncAttributeMaxDynamicSharedMemorySize, FC_SMEM_BYTES);

    pre_kernel<<<dim3(1024, 4, 1), 256>>>(query, key_, value, Wq, bq, Wk, bk, Wv, bv,
                                          relk, relv, Wfc, mask);
    attn_kernel<<<dim3(LL/QB, HH, BB), 128, ATT_SMEM_BYTES>>>();
    fc_kernel<<<dim3(32, 8, 1), 512, FC_SMEM_BYTES>>>(bfc, out);
}

// round 16
// speedup vs baseline: 1.2322x; 1.0178x over previous
#include <cuda_runtime.h>
#include <cuda_fp16.h>
#include <cstdint>
#include <cstddef>

#define BB   4
#define LL   1024
#define HH   16
#define DD   64
#define EMBN 1024
#define MAXREL 512
#define NREL (2*MAXREL + 1)

#define QB   64
#define SH   72    // half stride (pre smem)
#define SRS  200   // Srel ring stride: 192 slots + pad (100 words == 4 mod 32)
#define SBW  88    // band/Q buffer stride (44 words == 12 mod 32)
#define NEGBIG (-1.25e19f)

// swizzled stride-64 tile: element (row, col8-group)
#define SWZ(r,c8) (((r) << 6) + ((((c8) ^ ((r) & 7))) << 3))

// Scratch (allocation-free rule: device globals)
__device__ __half g_qh [BB*LL*HH*DD];
__device__ __half g_kh [BB*LL*HH*DD];
__device__ __half g_vh [BB*LL*HH*DD];
__device__ __half g_ctx[BB*LL*HH*DD];
__device__ __half g_relk_h[NREL*DD];
__device__ __half g_relv_h[NREL*DD];
__device__ __half g_Wfc_h[EMBN*EMBN];
__device__ unsigned long long g_maskb[BB*LL*16];   // 64 k-bits per (row, k-tile)

// ---------------------------------------------------------------------------
#define MMA_F16(d0,d1,d2,d3,a0,a1,a2,a3,b0,b1)                               \
    asm volatile("mma.sync.aligned.m16n8k16.row.col.f32.f16.f16.f32 "        \
                 "{%0,%1,%2,%3}, {%4,%5,%6,%7}, {%8,%9}, {%0,%1,%2,%3};"     \
                 : "+f"(d0), "+f"(d1), "+f"(d2), "+f"(d3)                    \
                 : "r"(a0), "r"(a1), "r"(a2), "r"(a3), "r"(b0), "r"(b1))

#define LDSM_X4(r0,r1,r2,r3,addr)                                            \
    asm volatile("ldmatrix.sync.aligned.m8n8.x4.shared.b16 {%0,%1,%2,%3}, [%4];" \
                 : "=r"(r0), "=r"(r1), "=r"(r2), "=r"(r3) : "r"(addr) : "memory")

#define LDSM_X4_T(r0,r1,r2,r3,addr)                                          \
    asm volatile("ldmatrix.sync.aligned.m8n8.x4.trans.shared.b16 {%0,%1,%2,%3}, [%4];" \
                 : "=r"(r0), "=r"(r1), "=r"(r2), "=r"(r3) : "r"(addr) : "memory")

#define STSM_X4(addr,r0,r1,r2,r3)                                            \
    asm volatile("stmatrix.sync.aligned.m8n8.x4.shared.b16 [%0], {%1,%2,%3,%4};" \
                 :: "r"(addr), "r"(r0), "r"(r1), "r"(r2), "r"(r3) : "memory")

#define CP16(dst,src)                                                        \
    asm volatile("cp.async.cg.shared.global [%0], [%1], 16;" :: "r"(dst), "l"(src))
#define CPCOMMIT()  asm volatile("cp.async.commit_group;")
#define CPWAITALL() asm volatile("cp.async.wait_group 0;" ::: "memory")
#define CPWAIT1()   asm volatile("cp.async.wait_group 1;" ::: "memory")

__device__ __forceinline__ uint32_t ldh2(const __half* p) { return *(const uint32_t*)p; }
__device__ __forceinline__ uint32_t s2u(const void* p) {
    return (uint32_t)__cvta_generic_to_shared(p);
}
__device__ __forceinline__ int clampdiff(int d) {
    return d < -MAXREL ? -MAXREL : (d > MAXREL ? MAXREL : d);
}
__device__ __forceinline__ int m3(int x) { return (x + 48) % 3; }   // x >= -48
__device__ __forceinline__ uint2 f4_to_h4(float4 v) {
    __half2 h0 = __floats2half2_rn(v.x, v.y);
    __half2 h1 = __floats2half2_rn(v.z, v.w);
    uint2 r; r.x = *(uint32_t*)&h0; r.y = *(uint32_t*)&h1; return r;
}
__device__ __forceinline__ uint32_t h2u(__half2 h) { return *(uint32_t*)&h; }

// ---------------------------------------------------------------------------
// Pre: projections via fp16 mma, 128 rows/block (y=0..2; Q pre-scaled 0.125)
//      + constants / mask pack (y=3). grid (512, 4).
// ---------------------------------------------------------------------------
__global__ __launch_bounds__(256) void pre_kernel(
    const float* __restrict__ query, const float* __restrict__ key_, const float* __restrict__ value,
    const float* __restrict__ Wq, const float* __restrict__ bq,
    const float* __restrict__ Wk, const float* __restrict__ bk,
    const float* __restrict__ Wv, const float* __restrict__ bv,
    const float* __restrict__ relk, const float* __restrict__ relv,
    const float* __restrict__ Wfc,  const int* __restrict__ mask)
{
    const int tid = threadIdx.x;

    if (blockIdx.y == 3) {
        const int stride = 512 * 256;
        const int base = blockIdx.x * 256 + tid;
        for (int i = base; i < NREL*DD/4; i += stride) {
            float4 a = *(const float4*)(relk + (size_t)i*4);
            float4 b = *(const float4*)(relv + (size_t)i*4);
            *(uint2*)(g_relk_h + (size_t)i*4) = f4_to_h4(a);
            *(uint2*)(g_relv_h + (size_t)i*4) = f4_to_h4(b);
        }
        for (int i = base; i < EMBN*EMBN/4; i += stride) {
            float4 w = *(const float4*)(Wfc + (size_t)i*4);
            *(uint2*)(g_Wfc_h + (size_t)i*4) = f4_to_h4(w);
        }
        for (int i = base; i < BB*LL*16; i += stride) {
            int row = i >> 4, w = i & 15;
            const int* mrow = mask + (size_t)row*LL + w*64;
            unsigned long long bits = 0ull;
            #pragma unroll
            for (int j = 0; j < 16; j++) {
                int4 v = *(const int4*)(mrow + j*4);
                bits |= (unsigned long long)(v.x != 0) << (4*j + 0);
                bits |= (unsigned long long)(v.y != 0) << (4*j + 1);
                bits |= (unsigned long long)(v.z != 0) << (4*j + 2);
                bits |= (unsigned long long)(v.w != 0) << (4*j + 3);
            }
            g_maskb[i] = bits;
        }
        return;
    }

    __shared__ __half Xs[128*SH];
    __shared__ __half Ws[64*SH];
    __shared__ float bs[64];

    const float* X; const float* W; const float* bias; __half* out;
    float oscale = 1.0f;
    if (blockIdx.y == 0)      { X = query; W = Wq; bias = bq; out = g_qh; oscale = 0.125f; }
    else if (blockIdx.y == 1) { X = key_;  W = Wk; bias = bk; out = g_kh; }
    else                      { X = value; W = Wv; bias = bv; out = g_vh; }

    const size_t r0 = (size_t)blockIdx.x * 128;
    const int warp = tid >> 5, lane = tid & 31;
    const int g = lane >> 2, t = lane & 3;
    const int wr = warp >> 2, wc = warp & 3;
    const int l7 = lane & 7, l15 = lane & 15;
    const int lq8 = (lane >> 3) << 3;
    const int lq16 = (lane >> 4) << 3;

    // stage 128 rows of X (8 float4/thread) + 64 rows of W (4 float4/thread)
    {
        const int rr = tid >> 2, cb = (tid & 3) << 4;
        #pragma unroll
        for (int hl = 0; hl < 2; hl++) {
            #pragma unroll
            for (int i = 0; i < 4; i++) {
                float4 v = *(const float4*)(X + (r0 + hl*64 + rr)*64 + cb + i*4);
                *(uint2*)&Xs[(hl*64 + rr)*SH + cb + i*4] = f4_to_h4(v);
            }
        }
        #pragma unroll
        for (int i = 0; i < 4; i++) {
            float4 w = *(const float4*)(W + (size_t)rr*64 + cb + i*4);
            *(uint2*)&Ws[rr*SH + cb + i*4] = f4_to_h4(w);
        }
    }
    if (tid < 64) bs[tid] = bias[tid];
    __syncthreads();

    // W B-fragments hoisted (reused for both row halves)
    uint32_t wb[2][2][4];
    #pragma unroll
    for (int nt = 0; nt < 2; nt++)
        #pragma unroll
        for (int ksp = 0; ksp < 2; ksp++) {
            uint32_t ad = s2u(Ws + (wc*16 + nt*8 + l7)*SH + ksp*32 + lq8);
            LDSM_X4(wb[nt][ksp][0], wb[nt][ksp][1], wb[nt][ksp][2], wb[nt][ksp][3], ad);
        }

    #pragma unroll
    for (int hl = 0; hl < 2; hl++) {
        uint32_t qa[2][4][4];
        #pragma unroll
        for (int mt = 0; mt < 2; mt++)
            #pragma unroll
            for (int ks = 0; ks < 4; ks++) {
                uint32_t ad = s2u(Xs + (hl*64 + wr*32 + mt*16 + l15)*SH + ks*16 + lq16);
                LDSM_X4(qa[mt][ks][0], qa[mt][ks][1], qa[mt][ks][2], qa[mt][ks][3], ad);
            }

        #pragma unroll
        for (int nt = 0; nt < 2; nt++) {
            float c0[4] = {0,0,0,0}, c1[4] = {0,0,0,0};
            #pragma unroll
            for (int ksp = 0; ksp < 2; ksp++) {
                const uint32_t b0 = wb[nt][ksp][0], b1 = wb[nt][ksp][1];
                const uint32_t b2 = wb[nt][ksp][2], b3 = wb[nt][ksp][3];
                MMA_F16(c0[0],c0[1],c0[2],c0[3], qa[0][2*ksp  ][0],qa[0][2*ksp  ][1],qa[0][2*ksp  ][2],qa[0][2*ksp  ][3], b0,b1);
                MMA_F16(c1[0],c1[1],c1[2],c1[3], qa[1][2*ksp  ][0],qa[1][2*ksp  ][1],qa[1][2*ksp  ][2],qa[1][2*ksp  ][3], b0,b1);
                MMA_F16(c0[0],c0[1],c0[2],c0[3], qa[0][2*ksp+1][0],qa[0][2*ksp+1][1],qa[0][2*ksp+1][2],qa[0][2*ksp+1][3], b2,b3);
                MMA_F16(c1[0],c1[1],c1[2],c1[3], qa[1][2*ksp+1][0],qa[1][2*ksp+1][1],qa[1][2*ksp+1][2],qa[1][2*ksp+1][3], b2,b3);
            }
            const int cb2 = wc*16 + nt*8 + 2*t;
            const float bv0 = bs[cb2], bv1 = bs[cb2 + 1];
            __half2 h00 = __floats2half2_rn((c0[0] + bv0)*oscale, (c0[1] + bv1)*oscale);
            __half2 h01 = __floats2half2_rn((c0[2] + bv0)*oscale, (c0[3] + bv1)*oscale);
            __half2 h10 = __floats2half2_rn((c1[0] + bv0)*oscale, (c1[1] + bv1)*oscale);
            __half2 h11 = __floats2half2_rn((c1[2] + bv0)*oscale, (c1[3] + bv1)*oscale);
            const size_t rb = r0 + hl*64 + wr*32;
            *(uint32_t*)(out + (rb      + g)*64 + cb2) = h2u(h00);
            *(uint32_t*)(out + (rb +  8 + g)*64 + cb2) = h2u(h01);
            *(uint32_t*)(out + (rb + 16 + g)*64 + cb2) = h2u(h10);
            *(uint32_t*)(out + (rb + 24 + g)*64 + cb2) = h2u(h11);
        }
    }
}

// ---------------------------------------------------------------------------
// Attention (round-13, unchanged): QB=64, 4 warps, 2 CTAs/SM.
// ---------------------------------------------------------------------------
#define ATT_SMEM_HALFS (64*SRS + 64*SBW + 9*4096)
#define ATT_SMEM_BYTES (ATT_SMEM_HALFS*2)

__device__ __forceinline__ void srel_block_gemm(
    const __half* Tk, __half* SrelH, const uint32_t qa[4][4],
    int rw, int pbS, int lane)
{
    const int l7 = lane & 7, l15 = lane & 15;
    const int lg3 = lane >> 3;
    const int lq16 = (lane >> 4) << 3;
    #pragma unroll
    for (int npp = 0; npp < 4; npp++) {
        float c0[4] = {0,0,0,0}, c1[4] = {0,0,0,0};
        #pragma unroll
        for (int ksp = 0; ksp < 2; ksp++) {
            uint32_t b0,b1,b2,b3;
            uint32_t ad = s2u(Tk + SWZ(npp*16 + l7, ksp*4 + lg3));
            LDSM_X4(b0,b1,b2,b3, ad);
            MMA_F16(c0[0],c0[1],c0[2],c0[3], qa[2*ksp  ][0],qa[2*ksp  ][1],qa[2*ksp  ][2],qa[2*ksp  ][3], b0,b1);
            MMA_F16(c0[0],c0[1],c0[2],c0[3], qa[2*ksp+1][0],qa[2*ksp+1][1],qa[2*ksp+1][2],qa[2*ksp+1][3], b2,b3);
            uint32_t ad2 = s2u(Tk + SWZ(npp*16 + 8 + l7, ksp*4 + lg3));
            LDSM_X4(b0,b1,b2,b3, ad2);
            MMA_F16(c1[0],c1[1],c1[2],c1[3], qa[2*ksp  ][0],qa[2*ksp  ][1],qa[2*ksp  ][2],qa[2*ksp  ][3], b0,b1);
            MMA_F16(c1[0],c1[1],c1[2],c1[3], qa[2*ksp+1][0],qa[2*ksp+1][1],qa[2*ksp+1][2],qa[2*ksp+1][3], b2,b3);
        }
        __half2 h0 = __floats2half2_rn(c0[0], c0[1]);
        __half2 h1 = __floats2half2_rn(c0[2], c0[3]);
        __half2 h2 = __floats2half2_rn(c1[0], c1[1]);
        __half2 h3 = __floats2half2_rn(c1[2], c1[3]);
        uint32_t sad = s2u(SrelH + (rw + l15)*SRS + pbS + npp*16 + lq16);
        STSM_X4(sad, h2u(h0), h2u(h1), h2u(h2), h2u(h3));
    }
}

__global__ __launch_bounds__(128, 2) void attn_kernel()
{
    extern __shared__ __half smh[];
    __half* SrelH = smh;
    __half* Bw    = SrelH + 64*SRS;
    __half* KhB   = Bw    + 64*SBW;
    __half* VhB   = KhB   + 2*4096;
    __half* TkB   = VhB   + 2*4096;
    __half* TrvB  = TkB   + 2*4096;

    const int b  = blockIdx.z;
    const int h  = blockIdx.y;
    const int bx = blockIdx.x;
    const int q0 = bx * QB;
    const int tid  = threadIdx.x;
    const int warp = tid >> 5, lane = tid & 31;
    const int g = lane >> 2, t = lane & 3;
    const int l7 = lane & 7, l15 = lane & 15;
    const int lg3 = lane >> 3;
    const int lq16 = (lane >> 4) << 3;
    const int tkk = ((lane >> 3) & 1) << 3;
    const int tn8 = lane >> 4;
    const int rw = warp * 16;
    const int row0 = rw + g, row1 = rw + g + 8;

    const int d00 = -q0;
    const int bb0 = -bx;

    #pragma unroll
    for (int i = 0; i < 4; i++) {
        int id = tid + i*128;
        int r = id >> 3, c8 = id & 7, c = c8 << 3;
        CP16(s2u(Bw + r*SBW + c),
             g_qh + (((size_t)((b*LL + q0 + r)*HH + h)) << 6) + c);
        CP16(s2u(KhB + SWZ(r, c8)),
             g_kh + (((size_t)((b*LL + r)*HH + h)) << 6) + c);
        CP16(s2u(VhB + SWZ(r, c8)),
             g_vh + (((size_t)((b*LL + r)*HH + h)) << 6) + c);
        int dfc = clampdiff(d00 + r);
        CP16(s2u(TkB + SWZ(r, c8)),
             g_relk_h + ((size_t)(dfc + MAXREL) << 6) + c);
        int dfh = clampdiff(d00 - 64 + r);
        CP16(s2u(TkB + 4096 + SWZ(r, c8)),
             g_relk_h + ((size_t)(dfh + MAXREL) << 6) + c);
        CP16(s2u(TrvB + m3(bb0-1)*4096 + SWZ(r, c8)),
             g_relv_h + ((size_t)(dfh + MAXREL) << 6) + c);
        CP16(s2u(TrvB + m3(bb0)*4096 + SWZ(r, c8)),
             g_relv_h + ((size_t)(dfc + MAXREL) << 6) + c);
    }
    CPCOMMIT(); CPWAITALL();
    __syncthreads();

    uint32_t qa[4][4];
    #pragma unroll
    for (int ks = 0; ks < 4; ks++) {
        uint32_t ad = s2u(Bw + (rw + l15)*SBW + ks*16 + lq16);
        LDSM_X4(qa[ks][0], qa[ks][1], qa[ks][2], qa[ks][3], ad);
    }
    __syncthreads();

    for (int i = tid; i < 64*SBW/8; i += 128) ((uint4*)Bw)[i] = make_uint4(0,0,0,0);

    srel_block_gemm(TkB + 4096, SrelH, qa, rw, m3(bb0-1)*64, lane);
    __syncthreads();

    float oacc[8][4] = {};
    float l0 = 0.f, l1 = 0.f;

    for (int kt = 0; kt < 16; kt++) {
        const int k0 = kt * 64;
        const int d0 = k0 - q0;
        const int bb = kt - bx;
        const int cs = kt & 1, ns = cs ^ 1;

        unsigned long long bits0 = g_maskb[((size_t)(b*LL + q0 + row0) << 4) + kt];
        unsigned long long bits1 = g_maskb[((size_t)(b*LL + q0 + row1) << 4) + kt];

        if (kt < 15) {
            const int k0n = k0 + 64;
            const int trvS = m3(bb + 1)*4096;
            #pragma unroll
            for (int i = 0; i < 4; i++) {
                int id = tid + i*128;
                int r = id >> 3, c8 = id & 7, c = c8 << 3;
                CP16(s2u(KhB + ns*4096 + SWZ(r, c8)),
                     g_kh + (((size_t)((b*LL + k0n + r)*HH + h)) << 6) + c);
                CP16(s2u(VhB + ns*4096 + SWZ(r, c8)),
                     g_vh + (((size_t)((b*LL + k0n + r)*HH + h)) << 6) + c);
                int df = clampdiff(d0 + 64 + r);
                CP16(s2u(TkB + ns*4096 + SWZ(r, c8)),
                     g_relk_h + ((size_t)(df + MAXREL) << 6) + c);
                CP16(s2u(TrvB + trvS + SWZ(r, c8)),
                     g_relv_h + ((size_t)(df + MAXREL) << 6) + c);
            }
            CPCOMMIT();
        }

        float s[8][4] = {};
        #pragma unroll
        for (int np = 0; np < 8; np++) {
            #pragma unroll
            for (int ksp = 0; ksp < 2; ksp++) {
                uint32_t b0,b1,b2,b3;
                uint32_t ad = s2u(KhB + cs*4096 + SWZ(np*8 + l7, ksp*4 + lg3));
                LDSM_X4(b0,b1,b2,b3, ad);
                MMA_F16(s[np][0],s[np][1],s[np][2],s[np][3],
                        qa[2*ksp  ][0],qa[2*ksp  ][1],qa[2*ksp  ][2],qa[2*ksp  ][3], b0,b1);
                MMA_F16(s[np][0],s[np][1],s[np][2],s[np][3],
                        qa[2*ksp+1][0],qa[2*ksp+1][1],qa[2*ksp+1][2],qa[2*ksp+1][3], b2,b3);
            }
        }
        srel_block_gemm(TkB + cs*4096, SrelH, qa, rw, m3(bb)*64, lane);
        __syncwarp();

        {
            const int sLo = m3(bb - 1)*64, sHi = m3(bb)*64;
            const __half* pA0 = SrelH + row0*SRS + sLo + 64 - row0;
            const __half* pB0 = SrelH + row0*SRS + sHi - row0;
            const __half* pA1 = SrelH + row1*SRS + sLo + 64 - row1;
            const __half* pB1 = SrelH + row1*SRS + sHi - row1;
            float ls0 = 0.f, ls1 = 0.f;
            #pragma unroll
            for (int np = 0; np < 8; np++) {
                #pragma unroll
                for (int i = 0; i < 2; i++) {
                    const int c = np*8 + 2*t + i;
                    float rel0 = __half2float((c < row0) ? pA0[c] : pB0[c]);
                    float rel1 = __half2float((c < row1) ? pA1[c] : pB1[c]);
                    float v0 = ((bits0 >> c) & 1ull) ? s[np][i]     : NEGBIG;
                    float v1 = ((bits1 >> c) & 1ull) ? s[np][2 + i] : NEGBIG;
                    float p0 = __expf(v0 + rel0);
                    float p1 = __expf(v1 + rel1);
                    s[np][i] = p0;  s[np][2 + i] = p1;
                    ls0 += p0;      ls1 += p1;
                }
            }
            ls0 += __shfl_xor_sync(0xffffffffu, ls0, 1);
            ls0 += __shfl_xor_sync(0xffffffffu, ls0, 2);
            ls1 += __shfl_xor_sync(0xffffffffu, ls1, 1);
            ls1 += __shfl_xor_sync(0xffffffffu, ls1, 2);
            l0 += ls0;  l1 += ls1;
        }

        uint32_t pa[4][4];
        #pragma unroll
        for (int ks = 0; ks < 4; ks++) {
            pa[ks][0] = h2u(__floats2half2_rn(s[2*ks  ][0], s[2*ks  ][1]));
            pa[ks][1] = h2u(__floats2half2_rn(s[2*ks  ][2], s[2*ks  ][3]));
            pa[ks][2] = h2u(__floats2half2_rn(s[2*ks+1][0], s[2*ks+1][1]));
            pa[ks][3] = h2u(__floats2half2_rn(s[2*ks+1][2], s[2*ks+1][3]));
        }
        #pragma unroll
        for (int np = 0; np < 8; np++) {
            #pragma unroll
            for (int i = 0; i < 2; i++) {
                const int c = np*8 + 2*t + i;
                Bw[row0*SBW + c - g + 15] = __float2half_rn(s[np][i]);
                Bw[row1*SBW + c - g +  7] = __float2half_rn(s[np][2 + i]);
            }
        }
        __syncwarp();

        #pragma unroll
        for (int ks = 0; ks < 4; ks++) {
            #pragma unroll
            for (int ndc = 0; ndc < 4; ndc++) {
                uint32_t b0,b1,b2,b3;
                uint32_t ad = s2u(VhB + cs*4096 + SWZ(ks*16 + tkk + l7, ndc*2 + tn8));
                LDSM_X4_T(b0,b1,b2,b3, ad);
                MMA_F16(oacc[2*ndc  ][0],oacc[2*ndc  ][1],oacc[2*ndc  ][2],oacc[2*ndc  ][3],
                        pa[ks][0],pa[ks][1],pa[ks][2],pa[ks][3], b0,b1);
                MMA_F16(oacc[2*ndc+1][0],oacc[2*ndc+1][1],oacc[2*ndc+1][2],oacc[2*ndc+1][3],
                        pa[ks][0],pa[ks][1],pa[ks][2],pa[ks][3], b2,b3);
            }
        }
        #pragma unroll
        for (int ks = 0; ks < 5; ks++) {
            uint32_t ua0,ua1,ua2,ua3;
            uint32_t aad = s2u(Bw + (rw + l15)*SBW + ks*16 + lq16);
            LDSM_X4(ua0,ua1,ua2,ua3, aad);
            int dd = d0 - 15 - rw + ks*16 + tkk + l7;
            if (dd > d0 + 63) dd = d0 + 63;
            int bdd = dd >> 6;
            int prow = m3(bdd)*64 + (dd & 63);
            #pragma unroll
            for (int ndc = 0; ndc < 4; ndc++) {
                uint32_t b0,b1,b2,b3;
                LDSM_X4_T(b0,b1,b2,b3, s2u(TrvB + SWZ(prow, ndc*2 + tn8)));
                MMA_F16(oacc[2*ndc  ][0],oacc[2*ndc  ][1],oacc[2*ndc  ][2],oacc[2*ndc  ][3],
                        ua0,ua1,ua2,ua3, b0,b1);
                MMA_F16(oacc[2*ndc+1][0],oacc[2*ndc+1][1],oacc[2*ndc+1][2],oacc[2*ndc+1][3],
                        ua0,ua1,ua2,ua3, b2,b3);
            }
        }

        CPWAITALL();
        __syncthreads();
    }

    {
        const float inv0 = 1.0f / l0;
        const float inv1 = 1.0f / l1;
        const size_t base0 = (((size_t)((b*LL + q0 + row0)*HH + h)) << 6);
        const size_t base1 = (((size_t)((b*LL + q0 + row1)*HH + h)) << 6);
        #pragma unroll
        for (int np = 0; np < 8; np++) {
            const int c = np*8 + 2*t;
            __half2 h0 = __floats2half2_rn(oacc[np][0]*inv0, oacc[np][1]*inv0);
            __half2 h1 = __floats2half2_rn(oacc[np][2]*inv1, oacc[np][3]*inv1);
            *(uint32_t*)(g_ctx + base0 + c) = h2u(h0);
            *(uint32_t*)(g_ctx + base1 + c) = h2u(h1);
        }
    }
}

// ---------------------------------------------------------------------------
// Final FC: 128x128 tiles, 512 threads, 2 CTAs/SM, cp.async double-buffered.
// ---------------------------------------------------------------------------
#define FCB 8192   // halves per buffer per array (128 x 64)
#define FC_SMEM_BYTES (4*FCB*2)

__global__ __launch_bounds__(512, 2) void fc_kernel(
    const float* __restrict__ bfc, float* __restrict__ out)
{
    extern __shared__ __half fcsm[];
    __half* Xs[2] = {fcsm,           fcsm + FCB};
    __half* Ws[2] = {fcsm + 2*FCB,   fcsm + 3*FCB};

    const int tid  = threadIdx.x;
    const int warp = tid >> 5, lane = tid & 31;
    const int g = lane >> 2, t = lane & 3;
    const int wr = warp >> 2, wc = warp & 3;
    const int l7 = lane & 7, l15 = lane & 15;
    const int lg3 = lane >> 3;
    const int ln16 = lane >> 4;
    const size_t r0 = (size_t)blockIdx.x * 128;
    const size_t n0 = (size_t)blockIdx.y * 128;

    float oacc[2][4][4] = {};

    #pragma unroll
    for (int i = 0; i < 2; i++) {
        int id = tid + i*512;
        int r = id >> 3, c8 = id & 7, c = c8 << 3;
        CP16(s2u(Xs[0] + SWZ(r, c8)), g_ctx   + (r0 + r)*EMBN + c);
        CP16(s2u(Ws[0] + SWZ(r, c8)), g_Wfc_h + (n0 + r)*EMBN + c);
    }
    CPCOMMIT();

    for (int e = 0; e < 16; e++) {
        const int cs = e & 1, ns = cs ^ 1;
        if (e < 15) {
            const int e0n = (e + 1) * 64;
            #pragma unroll
            for (int i = 0; i < 2; i++) {
                int id = tid + i*512;
                int r = id >> 3, c8 = id & 7, c = c8 << 3;
                CP16(s2u(Xs[ns] + SWZ(r, c8)), g_ctx   + (r0 + r)*EMBN + e0n + c);
                CP16(s2u(Ws[ns] + SWZ(r, c8)), g_Wfc_h + (n0 + r)*EMBN + e0n + c);
            }
            CPCOMMIT();
            CPWAIT1();
        } else {
            CPWAITALL();
        }
        __syncthreads();

        #pragma unroll
        for (int ksp = 0; ksp < 2; ksp++) {
            uint32_t a[2][2][4];
            #pragma unroll
            for (int mi = 0; mi < 2; mi++)
                #pragma unroll
                for (int kk = 0; kk < 2; kk++) {
                    uint32_t ad = s2u(Xs[cs] + SWZ(wr*32 + mi*16 + l15, (2*ksp + kk)*2 + ln16));
                    LDSM_X4(a[mi][kk][0], a[mi][kk][1], a[mi][kk][2], a[mi][kk][3], ad);
                }
            #pragma unroll
            for (int nt = 0; nt < 4; nt++) {
                uint32_t b0,b1,b2,b3;
                uint32_t ad = s2u(Ws[cs] + SWZ(wc*32 + nt*8 + l7, ksp*4 + lg3));
                LDSM_X4(b0,b1,b2,b3, ad);
                #pragma unroll
                for (int mi = 0; mi < 2; mi++) {
                    MMA_F16(oacc[mi][nt][0], oacc[mi][nt][1], oacc[mi][nt][2], oacc[mi][nt][3],
                            a[mi][0][0], a[mi][0][1], a[mi][0][2], a[mi][0][3], b0, b1);
                    MMA_F16(oacc[mi][nt][0], oacc[mi][nt][1], oacc[mi][nt][2], oacc[mi][nt][3],
                            a[mi][1][0], a[mi][1][1], a[mi][1][2], a[mi][1][3], b2, b3);
                }
            }
        }
        __syncthreads();
    }

    #pragma unroll
    for (int mi = 0; mi < 2; mi++) {
        size_t ra = r0 + wr*32 + mi*16 + g;
        #pragma unroll
        for (int nt = 0; nt < 4; nt++) {
            size_t c = n0 + wc*32 + nt*8 + 2*t;
            float bv0 = bfc[c], bv1 = bfc[c+1];
            *(float2*)(out + ra*EMBN + c) =
                make_float2(oacc[mi][nt][0] + bv0, oacc[mi][nt][1] + bv1);
            *(float2*)(out + (ra+8)*EMBN + c) =
                make_float2(oacc[mi][nt][2] + bv0, oacc[mi][nt][3] + bv1);
        }
    }
}

// ---------------------------------------------------------------------------
extern "C" void kernel_launch(void* const* d_in, const int* in_sizes, int n_in,
                              void* d_out, int out_size)
{
    const float* query = (const float*)d_in[0];
    const float* key_  = (const float*)d_in[1];
    const float* value = (const float*)d_in[2];
    const int*   mask  = (const int*)d_in[3];
    const float* Wq = (const float*)d_in[4];
    const float* bq = (const float*)d_in[5];
    const float* Wk = (const float*)d_in[6];
    const float* bk = (const float*)d_in[7];
    const float* Wv = (const float*)d_in[8];
    const float* bv = (const float*)d_in[9];
    const float* Wfc = (const float*)d_in[10];
    const float* bfc = (const float*)d_in[11];
    const float* relk = (const float*)d_in[12];
    const float* relv = (const float*)d_in[13];
    float* out = (float*)d_out;

    cudaFuncSetAttribute(attn_kernel, cudaFuncAttributeMaxDynamicSharedMemorySize, ATT_SMEM_BYTES);
    cudaFuncSetAttribute(fc_kernel,   cudaFuncAttributeMaxDynamicSharedMemorySize, FC_SMEM_BYTES);

    pre_kernel<<<dim3(512, 4, 1), 256>>>(query, key_, value, Wq, bq, Wk, bk, Wv, bv,
                                         relk, relv, Wfc, mask);
    attn_kernel<<<dim3(LL/QB, HH, BB), 128, ATT_SMEM_BYTES>>>();
    fc_kernel<<<dim3(32, 8, 1), 512, FC_SMEM_BYTES>>>(bfc, out);
}